// round 1
// baseline (speedup 1.0000x reference)
#include <cuda_runtime.h>
#include <math.h>

// Problem dims
#define B_ 4
#define S_ 1024
#define D_ 1024
#define H_ 16
#define DH_ 64
#define F_ 4096
#define M_ (B_*S_)   // 4096 rows

// ---------------- scratch (static device globals; no allocation) ----------------
__device__ float g_q  [M_*D_];
__device__ float g_k  [M_*D_];
__device__ float g_v  [M_*D_];
__device__ float g_att[M_*D_];
__device__ float g_tmp[M_*D_];
__device__ float g_o1 [M_*D_];
__device__ float g_o2 [M_*D_];
__device__ float g_ffn[M_*F_];
__device__ float g_wpq[D_*D_];
__device__ float g_wpk[D_*D_];
__device__ float g_wpv[D_*D_];

// ---------------- weight repack: (H, D, DH) -> (D, H*DH) ----------------
__global__ void pack_w_kernel(const float* __restrict__ w, float* __restrict__ out)
{
    int idx = blockIdx.x * 256 + threadIdx.x;      // over D_*D_ = 1M
    int d = idx >> 10;
    int n = idx & 1023;
    int h = n >> 6;
    int e = n & 63;
    out[idx] = w[h * (D_ * DH_) + d * DH_ + e];
}

// ---------------- SGEMM: C = A(MxK) * B(KxN) + bias[N], optional ReLU ----------------
// 128x128 block tile, BK=8, 256 threads, 8x8 per-thread microtile.
#define BM 128
#define BN 128
#define BK 8
#define TM 8
#define TN 8

__global__ void __launch_bounds__(256) sgemm_bias_kernel(
    const float* __restrict__ A, const float* __restrict__ Bm,
    const float* __restrict__ bias, float* __restrict__ C,
    int M, int N, int K, int relu)
{
    __shared__ __align__(16) float As[BK][BM];
    __shared__ __align__(16) float Bs[BK][BN];

    int bx = blockIdx.x;           // along N
    int by = blockIdx.y;           // along M
    int tid = threadIdx.x;
    int tx = tid & 15;             // 16 threads along N
    int ty = tid >> 4;             // 16 threads along M

    const float* Ab = A  + (size_t)by * BM * K;
    const float* Bb = Bm + bx * BN;

    // A tile load: 128 rows x 8 cols = 256 float4 (2 per row)
    int a_row = tid >> 1;
    int a_col = (tid & 1) * 4;
    // B tile load: 8 rows x 128 cols = 256 float4
    int b_row = tid >> 5;
    int b_col = (tid & 31) * 4;

    float acc[TM][TN];
#pragma unroll
    for (int i = 0; i < TM; i++)
#pragma unroll
        for (int j = 0; j < TN; j++) acc[i][j] = 0.f;

    for (int k0 = 0; k0 < K; k0 += BK) {
        float4 av = *(const float4*)(Ab + (size_t)a_row * K + k0 + a_col);
        As[a_col + 0][a_row] = av.x;
        As[a_col + 1][a_row] = av.y;
        As[a_col + 2][a_row] = av.z;
        As[a_col + 3][a_row] = av.w;
        float4 bv = *(const float4*)(Bb + (size_t)(k0 + b_row) * N + b_col);
        *(float4*)&Bs[b_row][b_col] = bv;
        __syncthreads();

#pragma unroll
        for (int kk = 0; kk < BK; kk++) {
            float a_frag[TM], b_frag[TN];
            float4 a0 = *(const float4*)&As[kk][ty * TM];
            float4 a1 = *(const float4*)&As[kk][ty * TM + 4];
            a_frag[0]=a0.x; a_frag[1]=a0.y; a_frag[2]=a0.z; a_frag[3]=a0.w;
            a_frag[4]=a1.x; a_frag[5]=a1.y; a_frag[6]=a1.z; a_frag[7]=a1.w;
            float4 b0 = *(const float4*)&Bs[kk][tx * TN];
            float4 b1 = *(const float4*)&Bs[kk][tx * TN + 4];
            b_frag[0]=b0.x; b_frag[1]=b0.y; b_frag[2]=b0.z; b_frag[3]=b0.w;
            b_frag[4]=b1.x; b_frag[5]=b1.y; b_frag[6]=b1.z; b_frag[7]=b1.w;
#pragma unroll
            for (int i = 0; i < TM; i++)
#pragma unroll
                for (int j = 0; j < TN; j++)
                    acc[i][j] += a_frag[i] * b_frag[j];
        }
        __syncthreads();
    }

    float* Cb = C + (size_t)(by * BM) * N + bx * BN;
#pragma unroll
    for (int i = 0; i < TM; i++) {
        int row = ty * TM + i;
#pragma unroll
        for (int j = 0; j < TN; j += 4) {
            int col = tx * TN + j;
            float4 r;
            r.x = acc[i][j + 0] + bias[bx * BN + col + 0];
            r.y = acc[i][j + 1] + bias[bx * BN + col + 1];
            r.z = acc[i][j + 2] + bias[bx * BN + col + 2];
            r.w = acc[i][j + 3] + bias[bx * BN + col + 3];
            if (relu) {
                r.x = fmaxf(r.x, 0.f); r.y = fmaxf(r.y, 0.f);
                r.z = fmaxf(r.z, 0.f); r.w = fmaxf(r.w, 0.f);
            }
            *(float4*)&Cb[(size_t)row * N + col] = r;
        }
    }
}

// ---------------- fused attention (flash-style, fp32) ----------------
// Q,K,V laid out (B*S, H*DH) row-major. One thread = one query row of one head.
// Block = 128 q rows of one (b, h). K/V tiles of 64 keys in smem.
#define KT 64

__global__ void __launch_bounds__(128) attn_kernel(
    const float* __restrict__ Q, const float* __restrict__ K,
    const float* __restrict__ V, float* __restrict__ O, int causal)
{
    int qt = blockIdx.x;            // 0..7
    int h  = blockIdx.y;            // 0..15
    int b  = blockIdx.z;            // 0..3
    int t  = threadIdx.x;           // 0..127
    int qrow = qt * 128 + t;        // global query index in sequence

    const float* Qp = Q + (size_t)b * S_ * D_ + h * DH_;
    const float* Kp = K + (size_t)b * S_ * D_ + h * DH_;
    const float* Vp = V + (size_t)b * S_ * D_ + h * DH_;

    __shared__ __align__(16) float ks[KT][DH_];
    __shared__ __align__(16) float vs[KT][DH_];

    float q[DH_];
#pragma unroll
    for (int d = 0; d < DH_; d += 4) {
        float4 v4 = *(const float4*)(Qp + (size_t)qrow * D_ + d);
        q[d] = v4.x; q[d + 1] = v4.y; q[d + 2] = v4.z; q[d + 3] = v4.w;
    }

    float acc[DH_];
#pragma unroll
    for (int d = 0; d < DH_; d++) acc[d] = 0.f;
    float m = -1e30f, l = 0.f;
    const float scale = 0.125f;     // 1/sqrt(64)

    int kend = causal ? (qt + 1) * 128 : S_;

    for (int k0 = 0; k0 < kend; k0 += KT) {
        // cooperative K/V tile load: 64 rows x 16 float4 each
        for (int i = t; i < KT * 16; i += 128) {
            int r = i >> 4;
            int c = (i & 15) * 4;
            *(float4*)&ks[r][c] = *(const float4*)(Kp + (size_t)(k0 + r) * D_ + c);
            *(float4*)&vs[r][c] = *(const float4*)(Vp + (size_t)(k0 + r) * D_ + c);
        }
        __syncthreads();

        for (int j = 0; j < KT; j++) {
            int kg = k0 + j;
            if (causal && kg > qrow) break;   // remaining keys masked (exp -> 0)
            float s = 0.f;
#pragma unroll
            for (int d = 0; d < DH_; d++) s += q[d] * ks[j][d];
            s *= scale;
            if (s > m) {                      // rare: rescale history
                float corr = __expf(m - s);
                l *= corr;
#pragma unroll
                for (int d = 0; d < DH_; d++) acc[d] *= corr;
                m = s;
            }
            float p = __expf(s - m);
            l += p;
#pragma unroll
            for (int d = 0; d < DH_; d++) acc[d] += p * vs[j][d];
        }
        __syncthreads();
    }

    float inv = 1.f / l;
    float* Op = O + (size_t)(b * S_ + qrow) * D_ + h * DH_;
#pragma unroll
    for (int d = 0; d < DH_; d += 4) {
        float4 r;
        r.x = acc[d] * inv; r.y = acc[d + 1] * inv;
        r.z = acc[d + 2] * inv; r.w = acc[d + 3] * inv;
        *(float4*)&Op[d] = r;
    }
}

// ---------------- fused residual add + LayerNorm (unbiased var, eps=1e-12) ----------------
__global__ void __launch_bounds__(256) add_ln_kernel(
    const float* __restrict__ x, const float* __restrict__ res,
    const float* __restrict__ gamma, const float* __restrict__ beta,
    float* __restrict__ out)
{
    __shared__ float row[D_];
    __shared__ float red[256];
    int r = blockIdx.x, t = threadIdx.x;
    const float* xr = x   + (size_t)r * D_;
    const float* rr = res + (size_t)r * D_;

    float s = 0.f;
    for (int i = t; i < D_; i += 256) {
        float v = xr[i] + rr[i];
        row[i] = v;
        s += v;
    }
    red[t] = s;
    __syncthreads();
    for (int o = 128; o > 0; o >>= 1) {
        if (t < o) red[t] += red[t + o];
        __syncthreads();
    }
    float mean = red[0] * (1.f / D_);
    __syncthreads();

    float vs = 0.f;
    for (int i = t; i < D_; i += 256) {
        float d = row[i] - mean;
        vs += d * d;
    }
    red[t] = vs;
    __syncthreads();
    for (int o = 128; o > 0; o >>= 1) {
        if (t < o) red[t] += red[t + o];
        __syncthreads();
    }
    float inv = rsqrtf(red[0] * (1.f / (D_ - 1)) + 1e-12f);

    for (int i = t; i < D_; i += 256)
        out[(size_t)r * D_ + i] = gamma[i] * (row[i] - mean) * inv + beta[i];
}

// ---------------- host orchestration ----------------
static void run_gemm(const float* A, const float* Bm, const float* bias, float* C,
                     int M, int N, int K, int relu)
{
    dim3 grid(N / BN, M / BM);
    sgemm_bias_kernel<<<grid, 256>>>(A, Bm, bias, C, M, N, K, relu);
}

extern "C" void kernel_launch(void* const* d_in, const int* in_sizes, int n_in,
                              void* d_out, int out_size)
{
    const float* dec   = (const float*)d_in[0];
    const float* enc   = (const float*)d_in[1];
    // d_in[2] = mask (deterministic causal tril) — applied analytically
    const float* sa_wq = (const float*)d_in[3];
    const float* sa_wk = (const float*)d_in[4];
    const float* sa_wv = (const float*)d_in[5];
    const float* sa_bq = (const float*)d_in[6];
    const float* sa_bk = (const float*)d_in[7];
    const float* sa_bv = (const float*)d_in[8];
    const float* sa_wo = (const float*)d_in[9];
    const float* sa_bo = (const float*)d_in[10];
    const float* ca_wq = (const float*)d_in[11];
    const float* ca_wk = (const float*)d_in[12];
    const float* ca_wv = (const float*)d_in[13];
    const float* ca_bq = (const float*)d_in[14];
    const float* ca_bk = (const float*)d_in[15];
    const float* ca_bv = (const float*)d_in[16];
    const float* ca_wo = (const float*)d_in[17];
    const float* ca_bo = (const float*)d_in[18];
    const float* ff_w1 = (const float*)d_in[19];
    const float* ff_b1 = (const float*)d_in[20];
    const float* ff_w2 = (const float*)d_in[21];
    const float* ff_b2 = (const float*)d_in[22];
    const float* ln1g  = (const float*)d_in[23];
    const float* ln1b  = (const float*)d_in[24];
    const float* ln2g  = (const float*)d_in[25];
    const float* ln2b  = (const float*)d_in[26];
    const float* ln3g  = (const float*)d_in[27];
    const float* ln3b  = (const float*)d_in[28];
    float* out = (float*)d_out;

    float *q, *k, *v, *att, *tmp, *o1, *o2, *ffn, *wpq, *wpk, *wpv;
    cudaGetSymbolAddress((void**)&q,   g_q);
    cudaGetSymbolAddress((void**)&k,   g_k);
    cudaGetSymbolAddress((void**)&v,   g_v);
    cudaGetSymbolAddress((void**)&att, g_att);
    cudaGetSymbolAddress((void**)&tmp, g_tmp);
    cudaGetSymbolAddress((void**)&o1,  g_o1);
    cudaGetSymbolAddress((void**)&o2,  g_o2);
    cudaGetSymbolAddress((void**)&ffn, g_ffn);
    cudaGetSymbolAddress((void**)&wpq, g_wpq);
    cudaGetSymbolAddress((void**)&wpk, g_wpk);
    cudaGetSymbolAddress((void**)&wpv, g_wpv);

    const int packBlocks = (D_ * D_) / 256;
    dim3 attnGrid(S_ / 128, H_, B_);

    // ===== self-attention =====
    pack_w_kernel<<<packBlocks, 256>>>(sa_wq, wpq);
    pack_w_kernel<<<packBlocks, 256>>>(sa_wk, wpk);
    pack_w_kernel<<<packBlocks, 256>>>(sa_wv, wpv);
    run_gemm(dec, wpq, sa_bq, q, M_, D_, D_, 0);
    run_gemm(dec, wpk, sa_bk, k, M_, D_, D_, 0);
    run_gemm(dec, wpv, sa_bv, v, M_, D_, D_, 0);
    attn_kernel<<<attnGrid, 128>>>(q, k, v, att, 1);
    run_gemm(att, sa_wo, sa_bo, tmp, M_, D_, D_, 0);
    add_ln_kernel<<<M_, 256>>>(tmp, dec, ln1g, ln1b, o1);

    // ===== cross-attention =====
    pack_w_kernel<<<packBlocks, 256>>>(ca_wq, wpq);
    pack_w_kernel<<<packBlocks, 256>>>(ca_wk, wpk);
    pack_w_kernel<<<packBlocks, 256>>>(ca_wv, wpv);
    run_gemm(o1,  wpq, ca_bq, q, M_, D_, D_, 0);
    run_gemm(enc, wpk, ca_bk, k, M_, D_, D_, 0);
    run_gemm(enc, wpv, ca_bv, v, M_, D_, D_, 0);
    attn_kernel<<<attnGrid, 128>>>(q, k, v, att, 0);
    run_gemm(att, ca_wo, ca_bo, tmp, M_, D_, D_, 0);
    add_ln_kernel<<<M_, 256>>>(tmp, o1, ln2g, ln2b, o2);

    // ===== feed-forward =====
    run_gemm(o2,  ff_w1, ff_b1, ffn, M_, F_, D_, 1);   // + ReLU
    run_gemm(ffn, ff_w2, ff_b2, tmp, M_, D_, F_, 0);
    add_ln_kernel<<<M_, 256>>>(tmp, o2, ln3g, ln3b, out);
}

// round 3
// speedup vs baseline: 1.7970x; 1.7970x over previous
#include <cuda_runtime.h>
#include <cuda_fp16.h>
#include <math.h>

// Problem dims
#define B_ 4
#define S_ 1024
#define D_ 1024
#define H_ 16
#define DH_ 64
#define F_ 4096
#define M_ (B_*S_)   // 4096 rows

typedef unsigned int u32;
typedef unsigned long long u64;

// ---------------- scratch (static device globals; no allocation) ----------------
__device__ float  g_q  [M_*D_];
__device__ float  g_k  [M_*D_];
__device__ float  g_v  [M_*D_];
__device__ float  g_att[M_*D_];
__device__ float  g_tmp[M_*D_];
__device__ float  g_o1 [M_*D_];
__device__ float  g_o2 [M_*D_];
__device__ float  g_ffn[M_*F_];
__device__ __half g_ah [M_*F_];   // activation hi (fp16)
__device__ __half g_al [M_*F_];   // activation lo (fp16)
__device__ __half g_wh [D_*F_];   // weight^T hi
__device__ __half g_wl [D_*F_];   // weight^T lo

// ======================= PTX helpers (baseline ISA only) =======================
__device__ __forceinline__ u32 smem_u32(const void* p) {
    u32 r;
    asm("{ .reg .u64 t; cvta.to.shared.u64 t, %1; cvt.u32.u64 %0, t; }"
        : "=r"(r) : "l"(p));
    return r;
}

__device__ __forceinline__ void cp16(u32 dst, const void* src) {
    asm volatile("cp.async.cg.shared.global [%0], [%1], 16;" :: "r"(dst), "l"(src));
}
#define CP_COMMIT()  asm volatile("cp.async.commit_group;" ::: "memory")
#define CP_WAIT(n)   asm volatile("cp.async.wait_group %0;" :: "n"(n) : "memory")

__device__ __forceinline__ void ldm4(u32* r, u32 a) {
    asm volatile("ldmatrix.sync.aligned.m8n8.x4.shared.b16 {%0,%1,%2,%3}, [%4];"
        : "=r"(r[0]), "=r"(r[1]), "=r"(r[2]), "=r"(r[3]) : "r"(a));
}

__device__ __forceinline__ void mma16816(float* c, const u32* a, const u32* b) {
    asm volatile(
        "mma.sync.aligned.m16n8k16.row.col.f32.f16.f16.f32 "
        "{%0,%1,%2,%3}, {%4,%5,%6,%7}, {%8,%9}, {%0,%1,%2,%3};"
        : "+f"(c[0]), "+f"(c[1]), "+f"(c[2]), "+f"(c[3])
        : "r"(a[0]), "r"(a[1]), "r"(a[2]), "r"(a[3]), "r"(b[0]), "r"(b[1]));
}

// ======================= prep kernels (fp16 hi/lo split) =======================
struct __align__(8) h2x2 { __half2 a, b; };

__global__ void __launch_bounds__(256) round_split_h(
    const float* __restrict__ x, __half* __restrict__ hi, __half* __restrict__ lo)
{
    int i = blockIdx.x * 256 + threadIdx.x;     // one float4 per thread
    float4 v = ((const float4*)x)[i];
    __half hx = __float2half_rn(v.x), hy = __float2half_rn(v.y);
    __half hz = __float2half_rn(v.z), hw = __float2half_rn(v.w);
    __half lx = __float2half_rn(v.x - __half2float(hx));
    __half ly = __float2half_rn(v.y - __half2float(hy));
    __half lz = __float2half_rn(v.z - __half2float(hz));
    __half lw = __float2half_rn(v.w - __half2float(hw));
    h2x2 H; H.a = __halves2half2(hx, hy); H.b = __halves2half2(hz, hw);
    h2x2 L; L.a = __halves2half2(lx, ly); L.b = __halves2half2(lz, lw);
    ((h2x2*)hi)[i] = H;
    ((h2x2*)lo)[i] = L;
}

// (H, D, DH) -> transposed [N=H*DH][K=D], split hi/lo fp16
__global__ void __launch_bounds__(1024) tqkv_split_h(
    const float* __restrict__ w, __half* __restrict__ hi, __half* __restrict__ lo)
{
    __shared__ __half sh[32][36], sl[32][36];
    int tx = threadIdx.x, ty = threadIdx.y;
    int dt = blockIdx.x, et = blockIdx.y, h = blockIdx.z;
    int d = dt * 32 + ty, e = et * 32 + tx;
    float x = w[((size_t)h * D_ + d) * DH_ + e];
    __half hx = __float2half_rn(x);
    sh[ty][tx] = hx;
    sl[ty][tx] = __float2half_rn(x - __half2float(hx));
    __syncthreads();
    int n  = h * DH_ + et * 32 + ty;
    int dd = dt * 32 + tx;
    hi[(size_t)n * D_ + dd] = sh[tx][ty];
    lo[(size_t)n * D_ + dd] = sl[tx][ty];
}

// [R][C] -> [C][R], split hi/lo fp16
__global__ void __launch_bounds__(1024) trans_split_h(
    const float* __restrict__ in, __half* __restrict__ hi, __half* __restrict__ lo,
    int R, int C)
{
    __shared__ __half sh[32][36], sl[32][36];
    int tx = threadIdx.x, ty = threadIdx.y;
    int r = blockIdx.y * 32 + ty, c = blockIdx.x * 32 + tx;
    float x = in[(size_t)r * C + c];
    __half hx = __float2half_rn(x);
    sh[ty][tx] = hx;
    sl[ty][tx] = __float2half_rn(x - __half2float(hx));
    __syncthreads();
    int ro = blockIdx.x * 32 + ty, co = blockIdx.y * 32 + tx;
    hi[(size_t)ro * R + co] = sh[tx][ty];
    lo[(size_t)ro * R + co] = sl[tx][ty];
}

// ======================= fp16x3 mma.sync GEMM =======================
// C[M][N] = A[M][K] * Bt[N][K]^T + bias (3 products: hh + hl + lh)
// CTA 128x128, BK=32, 8 warps (2x4), warp tile 64x32, 3-stage cp.async pipe.
// Stage layout (32KB): Ah[128][32] @0, Al @8K, Bh[128][32] @16K, Bl @24K.
// Row = 64B (32 halves) = 4 chunks of 16B; swizzle: chunk ^= (row>>1)&3.
#define GSTG   3
#define GSTGB  32768u
#define GSMEM  (3 * 32768)

__device__ __forceinline__ void g_ld_stage(
    u32 sb, int s, int tid,
    const __half* Ahb, const __half* Alb,
    const __half* Bhb, const __half* Blb, int K, int k0)
{
    u32 st = sb + (u32)(s % GSTG) * GSTGB;
#pragma unroll
    for (int t = 0; t < 2; t++) {
        int i = tid + (t << 8);
        int row = i >> 2, ch = i & 3;
        u32 so = (u32)row * 64 + (u32)((ch ^ ((row >> 1) & 3)) << 4);
        size_t go = (size_t)row * K + k0 + ch * 8;
        cp16(st +         so, Ahb + go);
        cp16(st +  8192 + so, Alb + go);
        cp16(st + 16384 + so, Bhb + go);
        cp16(st + 24576 + so, Blb + go);
    }
    CP_COMMIT();
}

__global__ void __launch_bounds__(256, 1) gemmh_kernel(
    const __half* __restrict__ Ah, const __half* __restrict__ Al,
    const __half* __restrict__ Bh, const __half* __restrict__ Bl,
    const float* __restrict__ bias, float* __restrict__ C,
    int N, int K, int relu)
{
    extern __shared__ char smraw[];
    u32 sb = smem_u32(smraw);

    int tid = threadIdx.x;
    int wid = tid >> 5, lane = tid & 31;
    int wm = wid >> 2, wn = wid & 3;          // 2 x 4 warp grid
    int bx = blockIdx.x, by = blockIdx.y;

    const __half* Ahb = Ah + (size_t)(by * 128) * K;
    const __half* Alb = Al + (size_t)(by * 128) * K;
    const __half* Bhb = Bh + (size_t)(bx * 128) * K;
    const __half* Blb = Bl + (size_t)(bx * 128) * K;

    float acc[4][4][4];
#pragma unroll
    for (int a = 0; a < 4; a++)
#pragma unroll
        for (int b = 0; b < 4; b++)
#pragma unroll
            for (int c = 0; c < 4; c++) acc[a][b][c] = 0.f;

    const int NS = K >> 5;
    g_ld_stage(sb, 0, tid, Ahb, Alb, Bhb, Blb, K, 0);
    g_ld_stage(sb, 1, tid, Ahb, Alb, Bhb, Blb, K, 32);

    int mq = lane >> 3, r8 = lane & 7, sq = r8 >> 1;

    for (int s = 0; s < NS; s++) {
        if (s == NS - 1) CP_WAIT(0); else CP_WAIT(1);
        __syncthreads();
        if (s + 2 < NS)
            g_ld_stage(sb, s + 2, tid, Ahb, Alb, Bhb, Blb, K, (s + 2) * 32);

        u32 st = sb + (u32)(s % GSTG) * GSTGB;
#pragma unroll
        for (int kk = 0; kk < 2; kk++) {
            u32 asw = (u32)(((kk << 1) | (mq >> 1)) ^ sq);
            u32 arow = (u32)(wm * 64 + r8 + ((mq & 1) << 3));
            u32 aoff = st + arow * 64 + (asw << 4);
            u32 bsw = (u32)(((kk << 1) | (mq & 1)) ^ sq);
            u32 brow = (u32)(wn * 32 + r8 + ((mq >> 1) << 3));
            u32 boff = st + 16384 + brow * 64 + (bsw << 4);

            u32 ah4[4][4], al4[4][4];
#pragma unroll
            for (int mt = 0; mt < 4; mt++) {
                ldm4(ah4[mt], aoff + (u32)mt * 1024);
                ldm4(al4[mt], aoff + 8192 + (u32)mt * 1024);
            }
            u32 bh4[4][2], bl4[4][2];
            {
                u32 t4[4];
                ldm4(t4, boff);
                bh4[0][0]=t4[0]; bh4[0][1]=t4[1]; bh4[1][0]=t4[2]; bh4[1][1]=t4[3];
                ldm4(t4, boff + 1024);
                bh4[2][0]=t4[0]; bh4[2][1]=t4[1]; bh4[3][0]=t4[2]; bh4[3][1]=t4[3];
                ldm4(t4, boff + 8192);
                bl4[0][0]=t4[0]; bl4[0][1]=t4[1]; bl4[1][0]=t4[2]; bl4[1][1]=t4[3];
                ldm4(t4, boff + 8192 + 1024);
                bl4[2][0]=t4[0]; bl4[2][1]=t4[1]; bl4[3][0]=t4[2]; bl4[3][1]=t4[3];
            }
            // 3 independent passes of 16 MMAs each (hh, hl, lh)
#pragma unroll
            for (int mt = 0; mt < 4; mt++)
#pragma unroll
                for (int nt = 0; nt < 4; nt++)
                    mma16816(acc[mt][nt], ah4[mt], bh4[nt]);
#pragma unroll
            for (int mt = 0; mt < 4; mt++)
#pragma unroll
                for (int nt = 0; nt < 4; nt++)
                    mma16816(acc[mt][nt], ah4[mt], bl4[nt]);
#pragma unroll
            for (int mt = 0; mt < 4; mt++)
#pragma unroll
                for (int nt = 0; nt < 4; nt++)
                    mma16816(acc[mt][nt], al4[mt], bh4[nt]);
        }
    }

    // epilogue: registers -> global with fused bias (+ReLU)
    int gid = lane >> 2, tq = lane & 3;
#pragma unroll
    for (int mt = 0; mt < 4; mt++) {
        int row0 = by * 128 + wm * 64 + mt * 16 + gid;
#pragma unroll
        for (int nt = 0; nt < 4; nt++) {
            int col = bx * 128 + wn * 32 + nt * 8 + tq * 2;
            float b0 = bias[col], b1 = bias[col + 1];
            float2 v0, v1;
            v0.x = acc[mt][nt][0] + b0; v0.y = acc[mt][nt][1] + b1;
            v1.x = acc[mt][nt][2] + b0; v1.y = acc[mt][nt][3] + b1;
            if (relu) {
                v0.x = fmaxf(v0.x, 0.f); v0.y = fmaxf(v0.y, 0.f);
                v1.x = fmaxf(v1.x, 0.f); v1.y = fmaxf(v1.y, 0.f);
            }
            *(float2*)&C[(size_t)row0 * N + col]       = v0;
            *(float2*)&C[(size_t)(row0 + 8) * N + col] = v1;
        }
    }
}

// ---------------- fused attention (flash-style, fp32) ----------------
#define KT 64
__global__ void __launch_bounds__(128) attn_kernel(
    const float* __restrict__ Q, const float* __restrict__ K,
    const float* __restrict__ V, float* __restrict__ O, int causal)
{
    int qt = blockIdx.x;
    int h  = blockIdx.y;
    int b  = blockIdx.z;
    int t  = threadIdx.x;
    int qrow = qt * 128 + t;

    const float* Qp = Q + (size_t)b * S_ * D_ + h * DH_;
    const float* Kp = K + (size_t)b * S_ * D_ + h * DH_;
    const float* Vp = V + (size_t)b * S_ * D_ + h * DH_;

    __shared__ __align__(16) float ks[KT][DH_];
    __shared__ __align__(16) float vs[KT][DH_];

    float q[DH_];
#pragma unroll
    for (int d = 0; d < DH_; d += 4) {
        float4 v4 = *(const float4*)(Qp + (size_t)qrow * D_ + d);
        q[d] = v4.x; q[d + 1] = v4.y; q[d + 2] = v4.z; q[d + 3] = v4.w;
    }

    float acc[DH_];
#pragma unroll
    for (int d = 0; d < DH_; d++) acc[d] = 0.f;
    float m = -1e30f, l = 0.f;
    const float scale = 0.125f;

    int kend = causal ? (qt + 1) * 128 : S_;

    for (int k0 = 0; k0 < kend; k0 += KT) {
        for (int i = t; i < KT * 16; i += 128) {
            int r = i >> 4;
            int c = (i & 15) * 4;
            *(float4*)&ks[r][c] = *(const float4*)(Kp + (size_t)(k0 + r) * D_ + c);
            *(float4*)&vs[r][c] = *(const float4*)(Vp + (size_t)(k0 + r) * D_ + c);
        }
        __syncthreads();

        for (int j = 0; j < KT; j++) {
            int kg = k0 + j;
            if (causal && kg > qrow) break;
            float s = 0.f;
#pragma unroll
            for (int d = 0; d < DH_; d++) s += q[d] * ks[j][d];
            s *= scale;
            if (s > m) {
                float corr = __expf(m - s);
                l *= corr;
#pragma unroll
                for (int d = 0; d < DH_; d++) acc[d] *= corr;
                m = s;
            }
            float p = __expf(s - m);
            l += p;
#pragma unroll
            for (int d = 0; d < DH_; d++) acc[d] += p * vs[j][d];
        }
        __syncthreads();
    }

    float inv = 1.f / l;
    float* Op = O + (size_t)(b * S_ + qrow) * D_ + h * DH_;
#pragma unroll
    for (int d = 0; d < DH_; d += 4) {
        float4 r;
        r.x = acc[d] * inv; r.y = acc[d + 1] * inv;
        r.z = acc[d + 2] * inv; r.w = acc[d + 3] * inv;
        *(float4*)&Op[d] = r;
    }
}

// ---------------- fused residual add + LayerNorm ----------------
__global__ void __launch_bounds__(256) add_ln_kernel(
    const float* __restrict__ x, const float* __restrict__ res,
    const float* __restrict__ gamma, const float* __restrict__ beta,
    float* __restrict__ out)
{
    __shared__ float row[D_];
    __shared__ float red[256];
    int r = blockIdx.x, t = threadIdx.x;
    const float* xr = x   + (size_t)r * D_;
    const float* rr = res + (size_t)r * D_;

    float s = 0.f;
    for (int i = t; i < D_; i += 256) {
        float v = xr[i] + rr[i];
        row[i] = v;
        s += v;
    }
    red[t] = s;
    __syncthreads();
    for (int o = 128; o > 0; o >>= 1) {
        if (t < o) red[t] += red[t + o];
        __syncthreads();
    }
    float mean = red[0] * (1.f / D_);
    __syncthreads();

    float vs = 0.f;
    for (int i = t; i < D_; i += 256) {
        float d = row[i] - mean;
        vs += d * d;
    }
    red[t] = vs;
    __syncthreads();
    for (int o = 128; o > 0; o >>= 1) {
        if (t < o) red[t] += red[t + o];
        __syncthreads();
    }
    float inv = rsqrtf(red[0] * (1.f / (D_ - 1)) + 1e-12f);

    for (int i = t; i < D_; i += 256)
        out[(size_t)r * D_ + i] = gamma[i] * (row[i] - mean) * inv + beta[i];
}

// ---------------- host orchestration ----------------
static void run_gemmh(const __half* ah, const __half* al,
                      const __half* wh, const __half* wl,
                      const float* bias, float* C, int N, int K, int relu)
{
    dim3 grid(N / 128, M_ / 128);
    gemmh_kernel<<<grid, 256, GSMEM>>>(ah, al, wh, wl, bias, C, N, K, relu);
}

extern "C" void kernel_launch(void* const* d_in, const int* in_sizes, int n_in,
                              void* d_out, int out_size)
{
    const float* dec   = (const float*)d_in[0];
    const float* enc   = (const float*)d_in[1];
    // d_in[2] = mask (deterministic causal tril) — applied analytically
    const float* sa_wq = (const float*)d_in[3];
    const float* sa_wk = (const float*)d_in[4];
    const float* sa_wv = (const float*)d_in[5];
    const float* sa_bq = (const float*)d_in[6];
    const float* sa_bk = (const float*)d_in[7];
    const float* sa_bv = (const float*)d_in[8];
    const float* sa_wo = (const float*)d_in[9];
    const float* sa_bo = (const float*)d_in[10];
    const float* ca_wq = (const float*)d_in[11];
    const float* ca_wk = (const float*)d_in[12];
    const float* ca_wv = (const float*)d_in[13];
    const float* ca_bq = (const float*)d_in[14];
    const float* ca_bk = (const float*)d_in[15];
    const float* ca_bv = (const float*)d_in[16];
    const float* ca_wo = (const float*)d_in[17];
    const float* ca_bo = (const float*)d_in[18];
    const float* ff_w1 = (const float*)d_in[19];
    const float* ff_b1 = (const float*)d_in[20];
    const float* ff_w2 = (const float*)d_in[21];
    const float* ff_b2 = (const float*)d_in[22];
    const float* ln1g  = (const float*)d_in[23];
    const float* ln1b  = (const float*)d_in[24];
    const float* ln2g  = (const float*)d_in[25];
    const float* ln2b  = (const float*)d_in[26];
    const float* ln3g  = (const float*)d_in[27];
    const float* ln3b  = (const float*)d_in[28];
    float* out = (float*)d_out;

    float *q, *k, *v, *att, *tmp, *o1, *o2, *ffn;
    __half *ah, *al, *wh, *wl;
    cudaGetSymbolAddress((void**)&q,   g_q);
    cudaGetSymbolAddress((void**)&k,   g_k);
    cudaGetSymbolAddress((void**)&v,   g_v);
    cudaGetSymbolAddress((void**)&att, g_att);
    cudaGetSymbolAddress((void**)&tmp, g_tmp);
    cudaGetSymbolAddress((void**)&o1,  g_o1);
    cudaGetSymbolAddress((void**)&o2,  g_o2);
    cudaGetSymbolAddress((void**)&ffn, g_ffn);
    cudaGetSymbolAddress((void**)&ah,  g_ah);
    cudaGetSymbolAddress((void**)&al,  g_al);
    cudaGetSymbolAddress((void**)&wh,  g_wh);
    cudaGetSymbolAddress((void**)&wl,  g_wl);

    cudaFuncSetAttribute(gemmh_kernel, cudaFuncAttributeMaxDynamicSharedMemorySize, GSMEM);

    dim3 tb(32, 32);
    dim3 tqkvGrid(D_ / 32, DH_ / 32, H_);
    dim3 attnGrid(S_ / 128, H_, B_);
    const int rs4M  = (M_ * D_) / 1024;   // round_split blocks (float4 per thread)
    const int rs16M = (M_ * F_) / 1024;

    // ===== self-attention =====
    round_split_h<<<rs4M, 256>>>(dec, ah, al);
    tqkv_split_h<<<tqkvGrid, tb>>>(sa_wq, wh, wl);
    run_gemmh(ah, al, wh, wl, sa_bq, q, D_, D_, 0);
    tqkv_split_h<<<tqkvGrid, tb>>>(sa_wk, wh, wl);
    run_gemmh(ah, al, wh, wl, sa_bk, k, D_, D_, 0);
    tqkv_split_h<<<tqkvGrid, tb>>>(sa_wv, wh, wl);
    run_gemmh(ah, al, wh, wl, sa_bv, v, D_, D_, 0);
    attn_kernel<<<attnGrid, 128>>>(q, k, v, att, 1);
    round_split_h<<<rs4M, 256>>>(att, ah, al);
    trans_split_h<<<dim3(D_ / 32, D_ / 32), tb>>>(sa_wo, wh, wl, D_, D_);
    run_gemmh(ah, al, wh, wl, sa_bo, tmp, D_, D_, 0);
    add_ln_kernel<<<M_, 256>>>(tmp, dec, ln1g, ln1b, o1);

    // ===== cross-attention =====
    round_split_h<<<rs4M, 256>>>(o1, ah, al);
    tqkv_split_h<<<tqkvGrid, tb>>>(ca_wq, wh, wl);
    run_gemmh(ah, al, wh, wl, ca_bq, q, D_, D_, 0);
    round_split_h<<<rs4M, 256>>>(enc, ah, al);
    tqkv_split_h<<<tqkvGrid, tb>>>(ca_wk, wh, wl);
    run_gemmh(ah, al, wh, wl, ca_bk, k, D_, D_, 0);
    tqkv_split_h<<<tqkvGrid, tb>>>(ca_wv, wh, wl);
    run_gemmh(ah, al, wh, wl, ca_bv, v, D_, D_, 0);
    attn_kernel<<<attnGrid, 128>>>(q, k, v, att, 0);
    round_split_h<<<rs4M, 256>>>(att, ah, al);
    trans_split_h<<<dim3(D_ / 32, D_ / 32), tb>>>(ca_wo, wh, wl, D_, D_);
    run_gemmh(ah, al, wh, wl, ca_bo, tmp, D_, D_, 0);
    add_ln_kernel<<<M_, 256>>>(tmp, o1, ln2g, ln2b, o2);

    // ===== feed-forward =====
    round_split_h<<<rs4M, 256>>>(o2, ah, al);
    trans_split_h<<<dim3(F_ / 32, D_ / 32), tb>>>(ff_w1, wh, wl, D_, F_);
    run_gemmh(ah, al, wh, wl, ff_b1, ffn, F_, D_, 1);   // + ReLU
    round_split_h<<<rs16M, 256>>>(ffn, ah, al);
    trans_split_h<<<dim3(D_ / 32, F_ / 32), tb>>>(ff_w2, wh, wl, F_, D_);
    run_gemmh(ah, al, wh, wl, ff_b2, tmp, D_, F_, 0);
    add_ln_kernel<<<M_, 256>>>(tmp, o2, ln3g, ln3b, out);
}

// round 4
// speedup vs baseline: 3.0874x; 1.7181x over previous
#include <cuda_runtime.h>
#include <cuda_fp16.h>
#include <math.h>

// Problem dims
#define B_ 4
#define S_ 1024
#define D_ 1024
#define H_ 16
#define DH_ 64
#define F_ 4096
#define M_ (B_*S_)   // 4096 rows

typedef unsigned int u32;
typedef unsigned long long u64;

// ---------------- scratch (static device globals; no allocation) ----------------
__device__ float  g_tmp[M_*D_];
__device__ float  g_o1 [M_*D_];
__device__ float  g_o2 [M_*D_];
__device__ __half g_ah [M_*D_];   // activation hi (fp16)
__device__ __half g_al [M_*D_];   // activation lo
__device__ __half g_wh [D_*F_];   // weight^T hi
__device__ __half g_wl [D_*F_];   // weight^T lo
__device__ __half g_qh [M_*D_];
__device__ __half g_ql [M_*D_];
__device__ __half g_kh [M_*D_];
__device__ __half g_kl [M_*D_];
__device__ __half g_vh [M_*D_];
__device__ __half g_vl [M_*D_];
__device__ __half g_fh [M_*F_];   // FFN hidden hi
__device__ __half g_fl [M_*F_];

// ======================= PTX helpers (baseline ISA only) =======================
__device__ __forceinline__ u32 smem_u32(const void* p) {
    u32 r;
    asm("{ .reg .u64 t; cvta.to.shared.u64 t, %1; cvt.u32.u64 %0, t; }"
        : "=r"(r) : "l"(p));
    return r;
}

__device__ __forceinline__ void cp16(u32 dst, const void* src) {
    asm volatile("cp.async.cg.shared.global [%0], [%1], 16;" :: "r"(dst), "l"(src));
}
#define CP_COMMIT()  asm volatile("cp.async.commit_group;" ::: "memory")
#define CP_WAIT(n)   asm volatile("cp.async.wait_group %0;" :: "n"(n) : "memory")

__device__ __forceinline__ void ldm4(u32* r, u32 a) {
    asm volatile("ldmatrix.sync.aligned.m8n8.x4.shared.b16 {%0,%1,%2,%3}, [%4];"
        : "=r"(r[0]), "=r"(r[1]), "=r"(r[2]), "=r"(r[3]) : "r"(a));
}
__device__ __forceinline__ void ldm4t(u32* r, u32 a) {
    asm volatile("ldmatrix.sync.aligned.m8n8.x4.trans.shared.b16 {%0,%1,%2,%3}, [%4];"
        : "=r"(r[0]), "=r"(r[1]), "=r"(r[2]), "=r"(r[3]) : "r"(a));
}

__device__ __forceinline__ void mma16816(float* c, const u32* a, const u32* b) {
    asm volatile(
        "mma.sync.aligned.m16n8k16.row.col.f32.f16.f16.f32 "
        "{%0,%1,%2,%3}, {%4,%5,%6,%7}, {%8,%9}, {%0,%1,%2,%3};"
        : "+f"(c[0]), "+f"(c[1]), "+f"(c[2]), "+f"(c[3])
        : "r"(a[0]), "r"(a[1]), "r"(a[2]), "r"(a[3]), "r"(b[0]), "r"(b[1]));
}

// split (a,b) fp32 pair into packed fp16 hi and lo half2 words
__device__ __forceinline__ void pack2(float a, float b, u32& hi, u32& lo) {
    __half ha = __float2half_rn(a), hb = __float2half_rn(b);
    __half la = __float2half_rn(a - __half2float(ha));
    __half lb = __float2half_rn(b - __half2float(hb));
    __half2 Hh = __halves2half2(ha, hb), Ll = __halves2half2(la, lb);
    hi = *reinterpret_cast<u32*>(&Hh);
    lo = *reinterpret_cast<u32*>(&Ll);
}

// ======================= prep kernels (fp16 hi/lo split) =======================
struct __align__(8) h2x2 { __half2 a, b; };

__global__ void __launch_bounds__(256) round_split_h(
    const float* __restrict__ x, __half* __restrict__ hi, __half* __restrict__ lo)
{
    int i = blockIdx.x * 256 + threadIdx.x;
    float4 v = ((const float4*)x)[i];
    __half hx = __float2half_rn(v.x), hy = __float2half_rn(v.y);
    __half hz = __float2half_rn(v.z), hw = __float2half_rn(v.w);
    __half lx = __float2half_rn(v.x - __half2float(hx));
    __half ly = __float2half_rn(v.y - __half2float(hy));
    __half lz = __float2half_rn(v.z - __half2float(hz));
    __half lw = __float2half_rn(v.w - __half2float(hw));
    h2x2 Hh; Hh.a = __halves2half2(hx, hy); Hh.b = __halves2half2(hz, hw);
    h2x2 Ll; Ll.a = __halves2half2(lx, ly); Ll.b = __halves2half2(lz, lw);
    ((h2x2*)hi)[i] = Hh;
    ((h2x2*)lo)[i] = Ll;
}

// (H, D, DH) -> transposed [N=H*DH][K=D], split hi/lo fp16
__global__ void __launch_bounds__(1024) tqkv_split_h(
    const float* __restrict__ w, __half* __restrict__ hi, __half* __restrict__ lo)
{
    __shared__ __half sh[32][36], sl[32][36];
    int tx = threadIdx.x, ty = threadIdx.y;
    int dt = blockIdx.x, et = blockIdx.y, h = blockIdx.z;
    int d = dt * 32 + ty, e = et * 32 + tx;
    float x = w[((size_t)h * D_ + d) * DH_ + e];
    __half hx = __float2half_rn(x);
    sh[ty][tx] = hx;
    sl[ty][tx] = __float2half_rn(x - __half2float(hx));
    __syncthreads();
    int n  = h * DH_ + et * 32 + ty;
    int dd = dt * 32 + tx;
    hi[(size_t)n * D_ + dd] = sh[tx][ty];
    lo[(size_t)n * D_ + dd] = sl[tx][ty];
}

// [R][C] -> [C][R], split hi/lo fp16
__global__ void __launch_bounds__(1024) trans_split_h(
    const float* __restrict__ in, __half* __restrict__ hi, __half* __restrict__ lo,
    int R, int C)
{
    __shared__ __half sh[32][36], sl[32][36];
    int tx = threadIdx.x, ty = threadIdx.y;
    int r = blockIdx.y * 32 + ty, c = blockIdx.x * 32 + tx;
    float x = in[(size_t)r * C + c];
    __half hx = __float2half_rn(x);
    sh[ty][tx] = hx;
    sl[ty][tx] = __float2half_rn(x - __half2float(hx));
    __syncthreads();
    int ro = blockIdx.x * 32 + ty, co = blockIdx.y * 32 + tx;
    hi[(size_t)ro * R + co] = sh[tx][ty];
    lo[(size_t)ro * R + co] = sl[tx][ty];
}

// ======================= fp16x3 mma.sync GEMM =======================
// C = A(MxK) * Bt(NxK)^T + bias; 3 products (hh + hl + lh).
// CTA 128x128, BK=32, 8 warps (2x4), warp tile 64x32, 3-stage cp.async pipe.
// mode 0: fp32 C (+relu).  mode 1: write hi/lo fp16 pairs to Ch/Cl (+relu).
#define GSTG   3
#define GSTGB  32768u
#define GSMEM  (3 * 32768)

__device__ __forceinline__ void g_ld_stage(
    u32 sb, int s, int tid,
    const __half* Ahb, const __half* Alb,
    const __half* Bhb, const __half* Blb, int K, int k0)
{
    u32 st = sb + (u32)(s % GSTG) * GSTGB;
#pragma unroll
    for (int t = 0; t < 2; t++) {
        int i = tid + (t << 8);
        int row = i >> 2, ch = i & 3;
        u32 so = (u32)row * 64 + (u32)((ch ^ ((row >> 1) & 3)) << 4);
        size_t go = (size_t)row * K + k0 + ch * 8;
        cp16(st +         so, Ahb + go);
        cp16(st +  8192 + so, Alb + go);
        cp16(st + 16384 + so, Bhb + go);
        cp16(st + 24576 + so, Blb + go);
    }
    CP_COMMIT();
}

__global__ void __launch_bounds__(256, 1) gemmh_kernel(
    const __half* __restrict__ Ah, const __half* __restrict__ Al,
    const __half* __restrict__ Bh, const __half* __restrict__ Bl,
    const float* __restrict__ bias, float* __restrict__ C,
    __half* __restrict__ Ch, __half* __restrict__ Cl,
    int N, int K, int relu, int mode)
{
    extern __shared__ char smraw[];
    u32 sb = smem_u32(smraw);

    int tid = threadIdx.x;
    int wid = tid >> 5, lane = tid & 31;
    int wm = wid >> 2, wn = wid & 3;
    int bx = blockIdx.x, by = blockIdx.y;

    const __half* Ahb = Ah + (size_t)(by * 128) * K;
    const __half* Alb = Al + (size_t)(by * 128) * K;
    const __half* Bhb = Bh + (size_t)(bx * 128) * K;
    const __half* Blb = Bl + (size_t)(bx * 128) * K;

    float acc[4][4][4];
#pragma unroll
    for (int a = 0; a < 4; a++)
#pragma unroll
        for (int b = 0; b < 4; b++)
#pragma unroll
            for (int c = 0; c < 4; c++) acc[a][b][c] = 0.f;

    const int NS = K >> 5;
    g_ld_stage(sb, 0, tid, Ahb, Alb, Bhb, Blb, K, 0);
    g_ld_stage(sb, 1, tid, Ahb, Alb, Bhb, Blb, K, 32);

    int mq = lane >> 3, r8 = lane & 7, sq = r8 >> 1;

    for (int s = 0; s < NS; s++) {
        if (s == NS - 1) CP_WAIT(0); else CP_WAIT(1);
        __syncthreads();
        if (s + 2 < NS)
            g_ld_stage(sb, s + 2, tid, Ahb, Alb, Bhb, Blb, K, (s + 2) * 32);

        u32 st = sb + (u32)(s % GSTG) * GSTGB;
#pragma unroll
        for (int kk = 0; kk < 2; kk++) {
            u32 asw = (u32)(((kk << 1) | (mq >> 1)) ^ sq);
            u32 arow = (u32)(wm * 64 + r8 + ((mq & 1) << 3));
            u32 aoff = st + arow * 64 + (asw << 4);
            u32 bsw = (u32)(((kk << 1) | (mq & 1)) ^ sq);
            u32 brow = (u32)(wn * 32 + r8 + ((mq >> 1) << 3));
            u32 boff = st + 16384 + brow * 64 + (bsw << 4);

            u32 ah4[4][4], al4[4][4];
#pragma unroll
            for (int mt = 0; mt < 4; mt++) {
                ldm4(ah4[mt], aoff + (u32)mt * 1024);
                ldm4(al4[mt], aoff + 8192 + (u32)mt * 1024);
            }
            u32 bh4[4][2], bl4[4][2];
            {
                u32 t4[4];
                ldm4(t4, boff);
                bh4[0][0]=t4[0]; bh4[0][1]=t4[1]; bh4[1][0]=t4[2]; bh4[1][1]=t4[3];
                ldm4(t4, boff + 1024);
                bh4[2][0]=t4[0]; bh4[2][1]=t4[1]; bh4[3][0]=t4[2]; bh4[3][1]=t4[3];
                ldm4(t4, boff + 8192);
                bl4[0][0]=t4[0]; bl4[0][1]=t4[1]; bl4[1][0]=t4[2]; bl4[1][1]=t4[3];
                ldm4(t4, boff + 8192 + 1024);
                bl4[2][0]=t4[0]; bl4[2][1]=t4[1]; bl4[3][0]=t4[2]; bl4[3][1]=t4[3];
            }
#pragma unroll
            for (int mt = 0; mt < 4; mt++)
#pragma unroll
                for (int nt = 0; nt < 4; nt++)
                    mma16816(acc[mt][nt], ah4[mt], bh4[nt]);
#pragma unroll
            for (int mt = 0; mt < 4; mt++)
#pragma unroll
                for (int nt = 0; nt < 4; nt++)
                    mma16816(acc[mt][nt], ah4[mt], bl4[nt]);
#pragma unroll
            for (int mt = 0; mt < 4; mt++)
#pragma unroll
                for (int nt = 0; nt < 4; nt++)
                    mma16816(acc[mt][nt], al4[mt], bh4[nt]);
        }
    }

    int gid = lane >> 2, tq = lane & 3;
#pragma unroll
    for (int mt = 0; mt < 4; mt++) {
        int row0 = by * 128 + wm * 64 + mt * 16 + gid;
#pragma unroll
        for (int nt = 0; nt < 4; nt++) {
            int col = bx * 128 + wn * 32 + nt * 8 + tq * 2;
            float b0 = bias[col], b1 = bias[col + 1];
            float v0 = acc[mt][nt][0] + b0, v1 = acc[mt][nt][1] + b1;
            float v2 = acc[mt][nt][2] + b0, v3 = acc[mt][nt][3] + b1;
            if (relu) {
                v0 = fmaxf(v0, 0.f); v1 = fmaxf(v1, 0.f);
                v2 = fmaxf(v2, 0.f); v3 = fmaxf(v3, 0.f);
            }
            if (mode == 0) {
                *(float2*)&C[(size_t)row0 * N + col]       = make_float2(v0, v1);
                *(float2*)&C[(size_t)(row0 + 8) * N + col] = make_float2(v2, v3);
            } else {
                u32 h01, l01, h23, l23;
                pack2(v0, v1, h01, l01);
                pack2(v2, v3, h23, l23);
                *(u32*)(Ch + (size_t)row0 * N + col)       = h01;
                *(u32*)(Cl + (size_t)row0 * N + col)       = l01;
                *(u32*)(Ch + (size_t)(row0 + 8) * N + col) = h23;
                *(u32*)(Cl + (size_t)(row0 + 8) * N + col) = l23;
            }
        }
    }
}

// ======================= tensor-core flash attention =======================
// CTA: 128 q rows of one (b,h); 8 warps, each one m16 tile.
// K/V tiles of 64 keys; fp16 hi/lo x3 for both QK^T and PV; fp32 online softmax.
// smem: Qh[128][64] @0 (16KB), Ql @16K; stages @32K + st*32K:
//   Kh @0, Kl @8K, Vh @16K, Vl @24K (each [64][64] halves, swizzled 128B rows)
#define ASMEM (32768 + 3 * 32768)

__device__ __forceinline__ u32 aswz(int r, int ch) {
    return (u32)(r * 128 + ((ch ^ (r & 7)) << 4));
}

__device__ __forceinline__ void attn_ld_kv(
    u32 sb, int st, int tid,
    const __half* Kh, const __half* Kl, const __half* Vh, const __half* Vl,
    size_t hb, int k0)
{
    u32 base = sb + 32768 + (u32)st * 32768;
#pragma unroll
    for (int i = 0; i < 2; i++) {
        int idx = tid + (i << 8);
        int r = idx >> 3, ch = idx & 7;
        u32 so = aswz(r, ch);
        size_t go = hb + (size_t)(k0 + r) * D_ + ch * 8;
        cp16(base +         so, Kh + go);
        cp16(base +  8192 + so, Kl + go);
        cp16(base + 16384 + so, Vh + go);
        cp16(base + 24576 + so, Vl + go);
    }
    CP_COMMIT();
}

__global__ void __launch_bounds__(256, 1) attn_tc_kernel(
    const __half* __restrict__ Qh, const __half* __restrict__ Ql,
    const __half* __restrict__ Kh, const __half* __restrict__ Kl,
    const __half* __restrict__ Vh, const __half* __restrict__ Vl,
    __half* __restrict__ Oh, __half* __restrict__ Ol, int causal)
{
    extern __shared__ char smraw[];
    u32 sb = smem_u32(smraw);
    int tid = threadIdx.x, wid = tid >> 5, lane = tid & 31;
    int gid = lane >> 2, tq = lane & 3;
    int qt = blockIdx.x, h = blockIdx.y, b = blockIdx.z;

    const size_t hb = (size_t)b * S_ * D_ + h * DH_;   // (b, s=0, head base)

    // stage Q tile (hi+lo)
#pragma unroll
    for (int i = 0; i < 4; i++) {
        int idx = tid + (i << 8);
        int r = idx >> 3, ch = idx & 7;
        u32 so = aswz(r, ch);
        size_t go = hb + (size_t)(qt * 128 + r) * D_ + ch * 8;
        cp16(sb +         so, Qh + go);
        cp16(sb + 16384 + so, Ql + go);
    }
    CP_COMMIT();

    int ntiles = causal ? (qt + 1) * 2 : (S_ / 64);
    attn_ld_kv(sb, 0, tid, Kh, Kl, Vh, Vl, hb, 0);
    attn_ld_kv(sb, 1, tid, Kh, Kl, Vh, Vl, hb, 64);

    CP_WAIT(2);              // Q landed
    __syncthreads();

    u32 qhf[4][4], qlf[4][4];
#pragma unroll
    for (int ks = 0; ks < 4; ks++) {
        int r = wid * 16 + (lane & 15);
        int ch = 2 * ks + (lane >> 4);
        u32 so = aswz(r, ch);
        ldm4(qhf[ks], sb + so);
        ldm4(qlf[ks], sb + 16384 + so);
    }

    float oacc[8][4];
#pragma unroll
    for (int i = 0; i < 8; i++)
#pragma unroll
        for (int j = 0; j < 4; j++) oacc[i][j] = 0.f;
    float m0 = -1e30f, m1 = -1e30f, l0 = 0.f, l1 = 0.f;

    int r8 = lane & 7, mq = lane >> 3;

    for (int t = 0; t < ntiles; t++) {
        __syncthreads();
        if (t + 2 < ntiles) {
            attn_ld_kv(sb, (t + 2) % 3, tid, Kh, Kl, Vh, Vl, hb, (t + 2) * 64);
            CP_WAIT(2);
        } else if (t + 1 < ntiles) {
            CP_WAIT(1);
        } else {
            CP_WAIT(0);
        }
        __syncthreads();

        u32 stg = sb + 32768 + (u32)(t % 3) * 32768;

        // ---- S = Q K^T (3 products) ----
        float sacc[8][4];
#pragma unroll
        for (int i = 0; i < 8; i++)
#pragma unroll
            for (int j = 0; j < 4; j++) sacc[i][j] = 0.f;

#pragma unroll
        for (int ks = 0; ks < 4; ks++) {
#pragma unroll
            for (int ng = 0; ng < 4; ng++) {
                int row = ng * 16 + r8 + ((mq >> 1) << 3);
                int ch = 2 * ks + (mq & 1);
                u32 so = aswz(row, ch);
                u32 kh4[4], kl4[4];
                ldm4(kh4, stg + so);
                ldm4(kl4, stg + 8192 + so);
                mma16816(sacc[2 * ng],     qhf[ks], kh4);
                mma16816(sacc[2 * ng],     qhf[ks], kl4);
                mma16816(sacc[2 * ng],     qlf[ks], kh4);
                mma16816(sacc[2 * ng + 1], qhf[ks], kh4 + 2);
                mma16816(sacc[2 * ng + 1], qhf[ks], kl4 + 2);
                mma16816(sacc[2 * ng + 1], qlf[ks], kh4 + 2);
            }
        }

        // ---- scale + causal mask + online softmax ----
        int k0 = t * 64;
        int wrow = qt * 128 + wid * 16;
        bool dm = (causal != 0) && (k0 + 63 > wrow);
        float tm0 = -1e30f, tm1 = -1e30f;
#pragma unroll
        for (int nt = 0; nt < 8; nt++) {
#pragma unroll
            for (int c = 0; c < 4; c++) {
                float s = sacc[nt][c] * 0.125f;
                if (dm) {
                    int col = k0 + nt * 8 + 2 * tq + (c & 1);
                    int row = wrow + gid + ((c >= 2) ? 8 : 0);
                    if (col > row) s = -1e30f;
                }
                sacc[nt][c] = s;
            }
            tm0 = fmaxf(tm0, fmaxf(sacc[nt][0], sacc[nt][1]));
            tm1 = fmaxf(tm1, fmaxf(sacc[nt][2], sacc[nt][3]));
        }
        tm0 = fmaxf(tm0, __shfl_xor_sync(0xffffffffu, tm0, 1));
        tm0 = fmaxf(tm0, __shfl_xor_sync(0xffffffffu, tm0, 2));
        tm1 = fmaxf(tm1, __shfl_xor_sync(0xffffffffu, tm1, 1));
        tm1 = fmaxf(tm1, __shfl_xor_sync(0xffffffffu, tm1, 2));
        float mn0 = fmaxf(m0, tm0), mn1 = fmaxf(m1, tm1);
        float cf0 = __expf(m0 - mn0), cf1 = __expf(m1 - mn1);
        float rs0 = 0.f, rs1 = 0.f;
#pragma unroll
        for (int nt = 0; nt < 8; nt++) {
            float p0 = __expf(sacc[nt][0] - mn0);
            float p1 = __expf(sacc[nt][1] - mn0);
            float p2 = __expf(sacc[nt][2] - mn1);
            float p3 = __expf(sacc[nt][3] - mn1);
            sacc[nt][0] = p0; sacc[nt][1] = p1; sacc[nt][2] = p2; sacc[nt][3] = p3;
            rs0 += p0 + p1; rs1 += p2 + p3;
        }
        rs0 += __shfl_xor_sync(0xffffffffu, rs0, 1);
        rs0 += __shfl_xor_sync(0xffffffffu, rs0, 2);
        rs1 += __shfl_xor_sync(0xffffffffu, rs1, 1);
        rs1 += __shfl_xor_sync(0xffffffffu, rs1, 2);
        l0 = l0 * cf0 + rs0;
        l1 = l1 * cf1 + rs1;
        m0 = mn0; m1 = mn1;
#pragma unroll
        for (int nt = 0; nt < 8; nt++) {
            oacc[nt][0] *= cf0; oacc[nt][1] *= cf0;
            oacc[nt][2] *= cf1; oacc[nt][3] *= cf1;
        }

        // ---- O += P V (3 products); P frags straight from sacc ----
#pragma unroll
        for (int kt = 0; kt < 4; kt++) {
            u32 pha[4], pla[4];
            pack2(sacc[2 * kt][0],     sacc[2 * kt][1],     pha[0], pla[0]);
            pack2(sacc[2 * kt][2],     sacc[2 * kt][3],     pha[1], pla[1]);
            pack2(sacc[2 * kt + 1][0], sacc[2 * kt + 1][1], pha[2], pla[2]);
            pack2(sacc[2 * kt + 1][2], sacc[2 * kt + 1][3], pha[3], pla[3]);
#pragma unroll
            for (int dg = 0; dg < 4; dg++) {
                int row = 16 * kt + (lane & 15);
                int ch = 2 * dg + (lane >> 4);
                u32 so = aswz(row, ch);
                u32 vh4[4], vl4[4];
                ldm4t(vh4, stg + 16384 + so);
                ldm4t(vl4, stg + 24576 + so);
                mma16816(oacc[2 * dg],     pha, vh4);
                mma16816(oacc[2 * dg],     pha, vl4);
                mma16816(oacc[2 * dg],     pla, vh4);
                mma16816(oacc[2 * dg + 1], pha, vh4 + 2);
                mma16816(oacc[2 * dg + 1], pha, vl4 + 2);
                mma16816(oacc[2 * dg + 1], pla, vh4 + 2);
            }
        }
    }

    // ---- epilogue: normalize, split hi/lo, store ----
    float inv0 = 1.f / l0, inv1 = 1.f / l1;
    size_t a0 = (size_t)(b * S_ + qt * 128 + wid * 16 + gid) * D_ + h * DH_;
    size_t a8 = a0 + 8 * D_;
#pragma unroll
    for (int nt = 0; nt < 8; nt++) {
        int col = nt * 8 + 2 * tq;
        u32 h01, l01, h23, l23;
        pack2(oacc[nt][0] * inv0, oacc[nt][1] * inv0, h01, l01);
        pack2(oacc[nt][2] * inv1, oacc[nt][3] * inv1, h23, l23);
        *(u32*)(Oh + a0 + col) = h01;
        *(u32*)(Ol + a0 + col) = l01;
        *(u32*)(Oh + a8 + col) = h23;
        *(u32*)(Ol + a8 + col) = l23;
    }
}

// ---------------- fused residual add + LayerNorm ----------------
__global__ void __launch_bounds__(256) add_ln_kernel(
    const float* __restrict__ x, const float* __restrict__ res,
    const float* __restrict__ gamma, const float* __restrict__ beta,
    float* __restrict__ out)
{
    __shared__ float row[D_];
    __shared__ float red[256];
    int r = blockIdx.x, t = threadIdx.x;
    const float* xr = x   + (size_t)r * D_;
    const float* rr = res + (size_t)r * D_;

    float s = 0.f;
    for (int i = t; i < D_; i += 256) {
        float v = xr[i] + rr[i];
        row[i] = v;
        s += v;
    }
    red[t] = s;
    __syncthreads();
    for (int o = 128; o > 0; o >>= 1) {
        if (t < o) red[t] += red[t + o];
        __syncthreads();
    }
    float mean = red[0] * (1.f / D_);
    __syncthreads();

    float vs = 0.f;
    for (int i = t; i < D_; i += 256) {
        float d = row[i] - mean;
        vs += d * d;
    }
    red[t] = vs;
    __syncthreads();
    for (int o = 128; o > 0; o >>= 1) {
        if (t < o) red[t] += red[t + o];
        __syncthreads();
    }
    float inv = rsqrtf(red[0] * (1.f / (D_ - 1)) + 1e-12f);

    for (int i = t; i < D_; i += 256)
        out[(size_t)r * D_ + i] = gamma[i] * (row[i] - mean) * inv + beta[i];
}

// ---------------- host orchestration ----------------
static void run_gemmh(const __half* ah, const __half* al,
                      const __half* wh, const __half* wl,
                      const float* bias, float* C, __half* Ch, __half* Cl,
                      int N, int K, int relu, int mode)
{
    dim3 grid(N / 128, M_ / 128);
    gemmh_kernel<<<grid, 256, GSMEM>>>(ah, al, wh, wl, bias, C, Ch, Cl, N, K, relu, mode);
}

extern "C" void kernel_launch(void* const* d_in, const int* in_sizes, int n_in,
                              void* d_out, int out_size)
{
    const float* dec   = (const float*)d_in[0];
    const float* enc   = (const float*)d_in[1];
    // d_in[2] = mask (deterministic causal tril) — applied analytically
    const float* sa_wq = (const float*)d_in[3];
    const float* sa_wk = (const float*)d_in[4];
    const float* sa_wv = (const float*)d_in[5];
    const float* sa_bq = (const float*)d_in[6];
    const float* sa_bk = (const float*)d_in[7];
    const float* sa_bv = (const float*)d_in[8];
    const float* sa_wo = (const float*)d_in[9];
    const float* sa_bo = (const float*)d_in[10];
    const float* ca_wq = (const float*)d_in[11];
    const float* ca_wk = (const float*)d_in[12];
    const float* ca_wv = (const float*)d_in[13];
    const float* ca_bq = (const float*)d_in[14];
    const float* ca_bk = (const float*)d_in[15];
    const float* ca_bv = (const float*)d_in[16];
    const float* ca_wo = (const float*)d_in[17];
    const float* ca_bo = (const float*)d_in[18];
    const float* ff_w1 = (const float*)d_in[19];
    const float* ff_b1 = (const float*)d_in[20];
    const float* ff_w2 = (const float*)d_in[21];
    const float* ff_b2 = (const float*)d_in[22];
    const float* ln1g  = (const float*)d_in[23];
    const float* ln1b  = (const float*)d_in[24];
    const float* ln2g  = (const float*)d_in[25];
    const float* ln2b  = (const float*)d_in[26];
    const float* ln3g  = (const float*)d_in[27];
    const float* ln3b  = (const float*)d_in[28];
    float* out = (float*)d_out;

    float *tmp, *o1, *o2;
    __half *ah, *al, *wh, *wl, *qh, *ql, *kh, *kl, *vh, *vl, *fh, *fl;
    cudaGetSymbolAddress((void**)&tmp, g_tmp);
    cudaGetSymbolAddress((void**)&o1,  g_o1);
    cudaGetSymbolAddress((void**)&o2,  g_o2);
    cudaGetSymbolAddress((void**)&ah,  g_ah);
    cudaGetSymbolAddress((void**)&al,  g_al);
    cudaGetSymbolAddress((void**)&wh,  g_wh);
    cudaGetSymbolAddress((void**)&wl,  g_wl);
    cudaGetSymbolAddress((void**)&qh,  g_qh);
    cudaGetSymbolAddress((void**)&ql,  g_ql);
    cudaGetSymbolAddress((void**)&kh,  g_kh);
    cudaGetSymbolAddress((void**)&kl,  g_kl);
    cudaGetSymbolAddress((void**)&vh,  g_vh);
    cudaGetSymbolAddress((void**)&vl,  g_vl);
    cudaGetSymbolAddress((void**)&fh,  g_fh);
    cudaGetSymbolAddress((void**)&fl,  g_fl);

    cudaFuncSetAttribute(gemmh_kernel, cudaFuncAttributeMaxDynamicSharedMemorySize, GSMEM);
    cudaFuncSetAttribute(attn_tc_kernel, cudaFuncAttributeMaxDynamicSharedMemorySize, ASMEM);

    dim3 tb(32, 32);
    dim3 tqkvGrid(D_ / 32, DH_ / 32, H_);
    dim3 attnGrid(S_ / 128, H_, B_);
    const int rs4M = (M_ * D_) / 1024;

    // ===== self-attention =====
    round_split_h<<<rs4M, 256>>>(dec, ah, al);
    tqkv_split_h<<<tqkvGrid, tb>>>(sa_wq, wh, wl);
    run_gemmh(ah, al, wh, wl, sa_bq, 0, qh, ql, D_, D_, 0, 1);
    tqkv_split_h<<<tqkvGrid, tb>>>(sa_wk, wh, wl);
    run_gemmh(ah, al, wh, wl, sa_bk, 0, kh, kl, D_, D_, 0, 1);
    tqkv_split_h<<<tqkvGrid, tb>>>(sa_wv, wh, wl);
    run_gemmh(ah, al, wh, wl, sa_bv, 0, vh, vl, D_, D_, 0, 1);
    attn_tc_kernel<<<attnGrid, 256, ASMEM>>>(qh, ql, kh, kl, vh, vl, ah, al, 1);
    trans_split_h<<<dim3(D_ / 32, D_ / 32), tb>>>(sa_wo, wh, wl, D_, D_);
    run_gemmh(ah, al, wh, wl, sa_bo, tmp, 0, 0, D_, D_, 0, 0);
    add_ln_kernel<<<M_, 256>>>(tmp, dec, ln1g, ln1b, o1);

    // ===== cross-attention =====
    round_split_h<<<rs4M, 256>>>(o1, ah, al);
    tqkv_split_h<<<tqkvGrid, tb>>>(ca_wq, wh, wl);
    run_gemmh(ah, al, wh, wl, ca_bq, 0, qh, ql, D_, D_, 0, 1);
    round_split_h<<<rs4M, 256>>>(enc, ah, al);
    tqkv_split_h<<<tqkvGrid, tb>>>(ca_wk, wh, wl);
    run_gemmh(ah, al, wh, wl, ca_bk, 0, kh, kl, D_, D_, 0, 1);
    tqkv_split_h<<<tqkvGrid, tb>>>(ca_wv, wh, wl);
    run_gemmh(ah, al, wh, wl, ca_bv, 0, vh, vl, D_, D_, 0, 1);
    attn_tc_kernel<<<attnGrid, 256, ASMEM>>>(qh, ql, kh, kl, vh, vl, ah, al, 0);
    trans_split_h<<<dim3(D_ / 32, D_ / 32), tb>>>(ca_wo, wh, wl, D_, D_);
    run_gemmh(ah, al, wh, wl, ca_bo, tmp, 0, 0, D_, D_, 0, 0);
    add_ln_kernel<<<M_, 256>>>(tmp, o1, ln2g, ln2b, o2);

    // ===== feed-forward =====
    round_split_h<<<rs4M, 256>>>(o2, ah, al);
    trans_split_h<<<dim3(F_ / 32, D_ / 32), tb>>>(ff_w1, wh, wl, D_, F_);
    run_gemmh(ah, al, wh, wl, ff_b1, 0, fh, fl, F_, D_, 1, 1);   // + ReLU, hi/lo out
    trans_split_h<<<dim3(D_ / 32, F_ / 32), tb>>>(ff_w2, wh, wl, F_, D_);
    run_gemmh(fh, fl, wh, wl, ff_b2, tmp, 0, 0, D_, F_, 0, 0);
    add_ln_kernel<<<M_, 256>>>(tmp, o2, ln3g, ln3b, out);
}

// round 5
// speedup vs baseline: 3.2032x; 1.0375x over previous
#include <cuda_runtime.h>
#include <cuda_fp16.h>
#include <math.h>

// Problem dims
#define B_ 4
#define S_ 1024
#define D_ 1024
#define H_ 16
#define DH_ 64
#define F_ 4096
#define M_ (B_*S_)   // 4096 rows

typedef unsigned int u32;
typedef unsigned long long u64;

// ---------------- scratch (static device globals; no allocation) ----------------
__device__ float  g_tmp[M_*D_];
__device__ float  g_o1 [M_*D_];
__device__ float  g_o2 [M_*D_];
__device__ __half g_ah [M_*D_];   // activation hi (fp16)
__device__ __half g_al [M_*D_];   // activation lo
__device__ __half g_wh [D_*F_];   // weight^T hi
__device__ __half g_wl [D_*F_];   // weight^T lo
__device__ __half g_qh [M_*D_];
__device__ __half g_ql [M_*D_];
__device__ __half g_kh [M_*D_];
__device__ __half g_kl [M_*D_];
__device__ __half g_vh [M_*D_];
__device__ __half g_vl [M_*D_];
__device__ __half g_fh [M_*F_];   // FFN hidden hi
__device__ __half g_fl [M_*F_];

// ======================= PTX helpers (baseline ISA only) =======================
__device__ __forceinline__ u32 smem_u32(const void* p) {
    u32 r;
    asm("{ .reg .u64 t; cvta.to.shared.u64 t, %1; cvt.u32.u64 %0, t; }"
        : "=r"(r) : "l"(p));
    return r;
}

__device__ __forceinline__ void cp16(u32 dst, const void* src) {
    asm volatile("cp.async.cg.shared.global [%0], [%1], 16;" :: "r"(dst), "l"(src));
}
#define CP_COMMIT()  asm volatile("cp.async.commit_group;" ::: "memory")
#define CP_WAIT(n)   asm volatile("cp.async.wait_group %0;" :: "n"(n) : "memory")

__device__ __forceinline__ void ldm4(u32* r, u32 a) {
    asm volatile("ldmatrix.sync.aligned.m8n8.x4.shared.b16 {%0,%1,%2,%3}, [%4];"
        : "=r"(r[0]), "=r"(r[1]), "=r"(r[2]), "=r"(r[3]) : "r"(a));
}
__device__ __forceinline__ void ldm4t(u32* r, u32 a) {
    asm volatile("ldmatrix.sync.aligned.m8n8.x4.trans.shared.b16 {%0,%1,%2,%3}, [%4];"
        : "=r"(r[0]), "=r"(r[1]), "=r"(r[2]), "=r"(r[3]) : "r"(a));
}

__device__ __forceinline__ void mma16816(float* c, const u32* a, const u32* b) {
    asm volatile(
        "mma.sync.aligned.m16n8k16.row.col.f32.f16.f16.f32 "
        "{%0,%1,%2,%3}, {%4,%5,%6,%7}, {%8,%9}, {%0,%1,%2,%3};"
        : "+f"(c[0]), "+f"(c[1]), "+f"(c[2]), "+f"(c[3])
        : "r"(a[0]), "r"(a[1]), "r"(a[2]), "r"(a[3]), "r"(b[0]), "r"(b[1]));
}

// split (a,b) fp32 pair into packed fp16 hi and lo half2 words
__device__ __forceinline__ void pack2(float a, float b, u32& hi, u32& lo) {
    __half ha = __float2half_rn(a), hb = __float2half_rn(b);
    __half la = __float2half_rn(a - __half2float(ha));
    __half lb = __float2half_rn(b - __half2float(hb));
    __half2 Hh = __halves2half2(ha, hb), Ll = __halves2half2(la, lb);
    hi = *reinterpret_cast<u32*>(&Hh);
    lo = *reinterpret_cast<u32*>(&Ll);
}

// ======================= prep kernels (fp16 hi/lo split) =======================
struct __align__(8) h2x2 { __half2 a, b; };

__global__ void __launch_bounds__(256) round_split_h(
    const float* __restrict__ x, __half* __restrict__ hi, __half* __restrict__ lo)
{
    int i = blockIdx.x * 256 + threadIdx.x;
    float4 v = ((const float4*)x)[i];
    __half hx = __float2half_rn(v.x), hy = __float2half_rn(v.y);
    __half hz = __float2half_rn(v.z), hw = __float2half_rn(v.w);
    __half lx = __float2half_rn(v.x - __half2float(hx));
    __half ly = __float2half_rn(v.y - __half2float(hy));
    __half lz = __float2half_rn(v.z - __half2float(hz));
    __half lw = __float2half_rn(v.w - __half2float(hw));
    h2x2 Hh; Hh.a = __halves2half2(hx, hy); Hh.b = __halves2half2(hz, hw);
    h2x2 Ll; Ll.a = __halves2half2(lx, ly); Ll.b = __halves2half2(lz, lw);
    ((h2x2*)hi)[i] = Hh;
    ((h2x2*)lo)[i] = Ll;
}

// (H, D, DH) -> transposed [N=H*DH][K=D], split hi/lo fp16
__global__ void __launch_bounds__(1024) tqkv_split_h(
    const float* __restrict__ w, __half* __restrict__ hi, __half* __restrict__ lo)
{
    __shared__ __half sh[32][36], sl[32][36];
    int tx = threadIdx.x, ty = threadIdx.y;
    int dt = blockIdx.x, et = blockIdx.y, h = blockIdx.z;
    int d = dt * 32 + ty, e = et * 32 + tx;
    float x = w[((size_t)h * D_ + d) * DH_ + e];
    __half hx = __float2half_rn(x);
    sh[ty][tx] = hx;
    sl[ty][tx] = __float2half_rn(x - __half2float(hx));
    __syncthreads();
    int n  = h * DH_ + et * 32 + ty;
    int dd = dt * 32 + tx;
    hi[(size_t)n * D_ + dd] = sh[tx][ty];
    lo[(size_t)n * D_ + dd] = sl[tx][ty];
}

// [R][C] -> [C][R], split hi/lo fp16
__global__ void __launch_bounds__(1024) trans_split_h(
    const float* __restrict__ in, __half* __restrict__ hi, __half* __restrict__ lo,
    int R, int C)
{
    __shared__ __half sh[32][36], sl[32][36];
    int tx = threadIdx.x, ty = threadIdx.y;
    int r = blockIdx.y * 32 + ty, c = blockIdx.x * 32 + tx;
    float x = in[(size_t)r * C + c];
    __half hx = __float2half_rn(x);
    sh[ty][tx] = hx;
    sl[ty][tx] = __float2half_rn(x - __half2float(hx));
    __syncthreads();
    int ro = blockIdx.x * 32 + ty, co = blockIdx.y * 32 + tx;
    hi[(size_t)ro * R + co] = sh[tx][ty];
    lo[(size_t)ro * R + co] = sl[tx][ty];
}

// ======================= fp16x3 mma.sync GEMM =======================
// C = A(MxK) * Bt(NxK)^T + bias; 3 products (hh + hl + lh).
// CTA 128x256, BK=32, 8 warps (2x4), warp tile 64x64, 3-stage cp.async pipe.
// Stage (48KB): Ah[128][32]@0, Al@8K, Bh[256][32]@16K, Bl@32K. 64B rows,
// swizzle: chunk ^= (row>>1)&3.
// mode 0: fp32 C (+relu).  mode 1: write hi/lo fp16 pairs to Ch/Cl (+relu).
#define GSTG   3
#define GSTGB  49152u
#define GSMEM  (3 * 49152)

__device__ __forceinline__ void g_ld_stage(
    u32 sb, int s, int tid,
    const __half* Ahb, const __half* Alb,
    const __half* Bhb, const __half* Blb, int K, int k0)
{
    u32 st = sb + (u32)(s % GSTG) * GSTGB;
    // A: 128 rows x 4 chunks = 512 chunks (hi + lo)
#pragma unroll
    for (int t = 0; t < 2; t++) {
        int i = tid + (t << 8);
        int row = i >> 2, ch = i & 3;
        u32 so = (u32)row * 64 + (u32)((ch ^ ((row >> 1) & 3)) << 4);
        size_t go = (size_t)row * K + k0 + ch * 8;
        cp16(st +        so, Ahb + go);
        cp16(st + 8192 + so, Alb + go);
    }
    // B: 256 rows x 4 chunks = 1024 chunks (hi + lo)
#pragma unroll
    for (int t = 0; t < 4; t++) {
        int i = tid + (t << 8);
        int row = i >> 2, ch = i & 3;
        u32 so = (u32)row * 64 + (u32)((ch ^ ((row >> 1) & 3)) << 4);
        size_t go = (size_t)row * K + k0 + ch * 8;
        cp16(st + 16384 + so, Bhb + go);
        cp16(st + 32768 + so, Blb + go);
    }
    CP_COMMIT();
}

__global__ void __launch_bounds__(256, 1) gemmh_kernel(
    const __half* __restrict__ Ah, const __half* __restrict__ Al,
    const __half* __restrict__ Bh, const __half* __restrict__ Bl,
    const float* __restrict__ bias, float* __restrict__ C,
    __half* __restrict__ Ch, __half* __restrict__ Cl,
    int N, int K, int relu, int mode)
{
    extern __shared__ char smraw[];
    u32 sb = smem_u32(smraw);

    int tid = threadIdx.x;
    int wid = tid >> 5, lane = tid & 31;
    int wm = wid >> 2, wn = wid & 3;      // 2 x 4 warp grid, warp tile 64x64
    int bx = blockIdx.x, by = blockIdx.y;

    const __half* Ahb = Ah + (size_t)(by * 128) * K;
    const __half* Alb = Al + (size_t)(by * 128) * K;
    const __half* Bhb = Bh + (size_t)(bx * 256) * K;
    const __half* Blb = Bl + (size_t)(bx * 256) * K;

    float acc[4][8][4];
#pragma unroll
    for (int a = 0; a < 4; a++)
#pragma unroll
        for (int b = 0; b < 8; b++)
#pragma unroll
            for (int c = 0; c < 4; c++) acc[a][b][c] = 0.f;

    const int NS = K >> 5;
    g_ld_stage(sb, 0, tid, Ahb, Alb, Bhb, Blb, K, 0);
    g_ld_stage(sb, 1, tid, Ahb, Alb, Bhb, Blb, K, 32);

    int mq = lane >> 3, r8 = lane & 7, sq = r8 >> 1;

    for (int s = 0; s < NS; s++) {
        if (s == NS - 1) CP_WAIT(0); else CP_WAIT(1);
        __syncthreads();
        if (s + 2 < NS)
            g_ld_stage(sb, s + 2, tid, Ahb, Alb, Bhb, Blb, K, (s + 2) * 32);

        u32 st = sb + (u32)(s % GSTG) * GSTGB;
#pragma unroll
        for (int kk = 0; kk < 2; kk++) {
            u32 asw = (u32)(((kk << 1) | (mq >> 1)) ^ sq);
            u32 arow = (u32)(wm * 64 + r8 + ((mq & 1) << 3));
            u32 aoff = st + arow * 64 + (asw << 4);
            u32 bsw = (u32)(((kk << 1) | (mq & 1)) ^ sq);
            u32 brow = (u32)(wn * 64 + r8 + ((mq >> 1) << 3));
            u32 boff = st + 16384 + brow * 64 + (bsw << 4);

            u32 ah4[4][4], al4[4][4];
#pragma unroll
            for (int mt = 0; mt < 4; mt++) {
                ldm4(ah4[mt], aoff + (u32)mt * 1024);
                ldm4(al4[mt], aoff + 8192 + (u32)mt * 1024);
            }
            u32 bh4[8][2], bl4[8][2];
#pragma unroll
            for (int g = 0; g < 4; g++) {
                u32 t4[4];
                ldm4(t4, boff + (u32)g * 1024);
                bh4[2*g][0]=t4[0]; bh4[2*g][1]=t4[1];
                bh4[2*g+1][0]=t4[2]; bh4[2*g+1][1]=t4[3];
                ldm4(t4, boff + 16384 + (u32)g * 1024);
                bl4[2*g][0]=t4[0]; bl4[2*g][1]=t4[1];
                bl4[2*g+1][0]=t4[2]; bl4[2*g+1][1]=t4[3];
            }
#pragma unroll
            for (int mt = 0; mt < 4; mt++)
#pragma unroll
                for (int nt = 0; nt < 8; nt++)
                    mma16816(acc[mt][nt], ah4[mt], bh4[nt]);
#pragma unroll
            for (int mt = 0; mt < 4; mt++)
#pragma unroll
                for (int nt = 0; nt < 8; nt++)
                    mma16816(acc[mt][nt], ah4[mt], bl4[nt]);
#pragma unroll
            for (int mt = 0; mt < 4; mt++)
#pragma unroll
                for (int nt = 0; nt < 8; nt++)
                    mma16816(acc[mt][nt], al4[mt], bh4[nt]);
        }
    }

    int gid = lane >> 2, tq = lane & 3;
#pragma unroll
    for (int mt = 0; mt < 4; mt++) {
        int row0 = by * 128 + wm * 64 + mt * 16 + gid;
#pragma unroll
        for (int nt = 0; nt < 8; nt++) {
            int col = bx * 256 + wn * 64 + nt * 8 + tq * 2;
            float b0 = bias[col], b1 = bias[col + 1];
            float v0 = acc[mt][nt][0] + b0, v1 = acc[mt][nt][1] + b1;
            float v2 = acc[mt][nt][2] + b0, v3 = acc[mt][nt][3] + b1;
            if (relu) {
                v0 = fmaxf(v0, 0.f); v1 = fmaxf(v1, 0.f);
                v2 = fmaxf(v2, 0.f); v3 = fmaxf(v3, 0.f);
            }
            if (mode == 0) {
                *(float2*)&C[(size_t)row0 * N + col]       = make_float2(v0, v1);
                *(float2*)&C[(size_t)(row0 + 8) * N + col] = make_float2(v2, v3);
            } else {
                u32 h01, l01, h23, l23;
                pack2(v0, v1, h01, l01);
                pack2(v2, v3, h23, l23);
                *(u32*)(Ch + (size_t)row0 * N + col)       = h01;
                *(u32*)(Cl + (size_t)row0 * N + col)       = l01;
                *(u32*)(Ch + (size_t)(row0 + 8) * N + col) = h23;
                *(u32*)(Cl + (size_t)(row0 + 8) * N + col) = l23;
            }
        }
    }
}

// ======================= tensor-core flash attention =======================
// CTA: 128 q rows of one (b,h); 8 warps, each one m16 tile.
// K/V tiles of 64 keys; fp16 hi/lo x3 for both QK^T and PV; fp32 online softmax.
// smem: Qh[128][64] @0 (16KB), Ql @16K; stages @32K + st*32K:
//   Kh @0, Kl @8K, Vh @16K, Vl @24K (each [64][64] halves, swizzled 128B rows)
#define ASMEM (32768 + 3 * 32768)

__device__ __forceinline__ u32 aswz(int r, int ch) {
    return (u32)(r * 128 + ((ch ^ (r & 7)) << 4));
}

__device__ __forceinline__ void attn_ld_kv(
    u32 sb, int st, int tid,
    const __half* Kh, const __half* Kl, const __half* Vh, const __half* Vl,
    size_t hb, int k0)
{
    u32 base = sb + 32768 + (u32)st * 32768;
#pragma unroll
    for (int i = 0; i < 2; i++) {
        int idx = tid + (i << 8);
        int r = idx >> 3, ch = idx & 7;
        u32 so = aswz(r, ch);
        size_t go = hb + (size_t)(k0 + r) * D_ + ch * 8;
        cp16(base +         so, Kh + go);
        cp16(base +  8192 + so, Kl + go);
        cp16(base + 16384 + so, Vh + go);
        cp16(base + 24576 + so, Vl + go);
    }
    CP_COMMIT();
}

__global__ void __launch_bounds__(256, 1) attn_tc_kernel(
    const __half* __restrict__ Qh, const __half* __restrict__ Ql,
    const __half* __restrict__ Kh, const __half* __restrict__ Kl,
    const __half* __restrict__ Vh, const __half* __restrict__ Vl,
    __half* __restrict__ Oh, __half* __restrict__ Ol, int causal)
{
    extern __shared__ char smraw[];
    u32 sb = smem_u32(smraw);
    int tid = threadIdx.x, wid = tid >> 5, lane = tid & 31;
    int gid = lane >> 2, tq = lane & 3;
    int qt = blockIdx.x, h = blockIdx.y, b = blockIdx.z;

    const size_t hb = (size_t)b * S_ * D_ + h * DH_;   // (b, s=0, head base)

    // stage Q tile (hi+lo)
#pragma unroll
    for (int i = 0; i < 4; i++) {
        int idx = tid + (i << 8);
        int r = idx >> 3, ch = idx & 7;
        u32 so = aswz(r, ch);
        size_t go = hb + (size_t)(qt * 128 + r) * D_ + ch * 8;
        cp16(sb +         so, Qh + go);
        cp16(sb + 16384 + so, Ql + go);
    }
    CP_COMMIT();

    int ntiles = causal ? (qt + 1) * 2 : (S_ / 64);
    attn_ld_kv(sb, 0, tid, Kh, Kl, Vh, Vl, hb, 0);
    attn_ld_kv(sb, 1, tid, Kh, Kl, Vh, Vl, hb, 64);

    CP_WAIT(2);              // Q landed
    __syncthreads();

    u32 qhf[4][4], qlf[4][4];
#pragma unroll
    for (int ks = 0; ks < 4; ks++) {
        int r = wid * 16 + (lane & 15);
        int ch = 2 * ks + (lane >> 4);
        u32 so = aswz(r, ch);
        ldm4(qhf[ks], sb + so);
        ldm4(qlf[ks], sb + 16384 + so);
    }

    float oacc[8][4];
#pragma unroll
    for (int i = 0; i < 8; i++)
#pragma unroll
        for (int j = 0; j < 4; j++) oacc[i][j] = 0.f;
    float m0 = -1e30f, m1 = -1e30f, l0 = 0.f, l1 = 0.f;

    int r8 = lane & 7, mq = lane >> 3;

    for (int t = 0; t < ntiles; t++) {
        __syncthreads();
        if (t + 2 < ntiles) {
            attn_ld_kv(sb, (t + 2) % 3, tid, Kh, Kl, Vh, Vl, hb, (t + 2) * 64);
            CP_WAIT(2);
        } else if (t + 1 < ntiles) {
            CP_WAIT(1);
        } else {
            CP_WAIT(0);
        }
        __syncthreads();

        u32 stg = sb + 32768 + (u32)(t % 3) * 32768;

        // ---- S = Q K^T (3 products) ----
        float sacc[8][4];
#pragma unroll
        for (int i = 0; i < 8; i++)
#pragma unroll
            for (int j = 0; j < 4; j++) sacc[i][j] = 0.f;

#pragma unroll
        for (int ks = 0; ks < 4; ks++) {
#pragma unroll
            for (int ng = 0; ng < 4; ng++) {
                int row = ng * 16 + r8 + ((mq >> 1) << 3);
                int ch = 2 * ks + (mq & 1);
                u32 so = aswz(row, ch);
                u32 kh4[4], kl4[4];
                ldm4(kh4, stg + so);
                ldm4(kl4, stg + 8192 + so);
                mma16816(sacc[2 * ng],     qhf[ks], kh4);
                mma16816(sacc[2 * ng],     qhf[ks], kl4);
                mma16816(sacc[2 * ng],     qlf[ks], kh4);
                mma16816(sacc[2 * ng + 1], qhf[ks], kh4 + 2);
                mma16816(sacc[2 * ng + 1], qhf[ks], kl4 + 2);
                mma16816(sacc[2 * ng + 1], qlf[ks], kh4 + 2);
            }
        }

        // ---- scale + causal mask + online softmax ----
        int k0 = t * 64;
        int wrow = qt * 128 + wid * 16;
        bool dm = (causal != 0) && (k0 + 63 > wrow);
        float tm0 = -1e30f, tm1 = -1e30f;
#pragma unroll
        for (int nt = 0; nt < 8; nt++) {
#pragma unroll
            for (int c = 0; c < 4; c++) {
                float s = sacc[nt][c] * 0.125f;
                if (dm) {
                    int col = k0 + nt * 8 + 2 * tq + (c & 1);
                    int row = wrow + gid + ((c >= 2) ? 8 : 0);
                    if (col > row) s = -1e30f;
                }
                sacc[nt][c] = s;
            }
            tm0 = fmaxf(tm0, fmaxf(sacc[nt][0], sacc[nt][1]));
            tm1 = fmaxf(tm1, fmaxf(sacc[nt][2], sacc[nt][3]));
        }
        tm0 = fmaxf(tm0, __shfl_xor_sync(0xffffffffu, tm0, 1));
        tm0 = fmaxf(tm0, __shfl_xor_sync(0xffffffffu, tm0, 2));
        tm1 = fmaxf(tm1, __shfl_xor_sync(0xffffffffu, tm1, 1));
        tm1 = fmaxf(tm1, __shfl_xor_sync(0xffffffffu, tm1, 2));
        float mn0 = fmaxf(m0, tm0), mn1 = fmaxf(m1, tm1);
        float cf0 = __expf(m0 - mn0), cf1 = __expf(m1 - mn1);
        float rs0 = 0.f, rs1 = 0.f;
#pragma unroll
        for (int nt = 0; nt < 8; nt++) {
            float p0 = __expf(sacc[nt][0] - mn0);
            float p1 = __expf(sacc[nt][1] - mn0);
            float p2 = __expf(sacc[nt][2] - mn1);
            float p3 = __expf(sacc[nt][3] - mn1);
            sacc[nt][0] = p0; sacc[nt][1] = p1; sacc[nt][2] = p2; sacc[nt][3] = p3;
            rs0 += p0 + p1; rs1 += p2 + p3;
        }
        rs0 += __shfl_xor_sync(0xffffffffu, rs0, 1);
        rs0 += __shfl_xor_sync(0xffffffffu, rs0, 2);
        rs1 += __shfl_xor_sync(0xffffffffu, rs1, 1);
        rs1 += __shfl_xor_sync(0xffffffffu, rs1, 2);
        l0 = l0 * cf0 + rs0;
        l1 = l1 * cf1 + rs1;
        m0 = mn0; m1 = mn1;
#pragma unroll
        for (int nt = 0; nt < 8; nt++) {
            oacc[nt][0] *= cf0; oacc[nt][1] *= cf0;
            oacc[nt][2] *= cf1; oacc[nt][3] *= cf1;
        }

        // ---- O += P V (3 products); P frags straight from sacc ----
#pragma unroll
        for (int kt = 0; kt < 4; kt++) {
            u32 pha[4], pla[4];
            pack2(sacc[2 * kt][0],     sacc[2 * kt][1],     pha[0], pla[0]);
            pack2(sacc[2 * kt][2],     sacc[2 * kt][3],     pha[1], pla[1]);
            pack2(sacc[2 * kt + 1][0], sacc[2 * kt + 1][1], pha[2], pla[2]);
            pack2(sacc[2 * kt + 1][2], sacc[2 * kt + 1][3], pha[3], pla[3]);
#pragma unroll
            for (int dg = 0; dg < 4; dg++) {
                int row = 16 * kt + (lane & 15);
                int ch = 2 * dg + (lane >> 4);
                u32 so = aswz(row, ch);
                u32 vh4[4], vl4[4];
                ldm4t(vh4, stg + 16384 + so);
                ldm4t(vl4, stg + 24576 + so);
                mma16816(oacc[2 * dg],     pha, vh4);
                mma16816(oacc[2 * dg],     pha, vl4);
                mma16816(oacc[2 * dg],     pla, vh4);
                mma16816(oacc[2 * dg + 1], pha, vh4 + 2);
                mma16816(oacc[2 * dg + 1], pha, vl4 + 2);
                mma16816(oacc[2 * dg + 1], pla, vh4 + 2);
            }
        }
    }

    // ---- epilogue: normalize, split hi/lo, store ----
    float inv0 = 1.f / l0, inv1 = 1.f / l1;
    size_t a0 = (size_t)(b * S_ + qt * 128 + wid * 16 + gid) * D_ + h * DH_;
    size_t a8 = a0 + 8 * D_;
#pragma unroll
    for (int nt = 0; nt < 8; nt++) {
        int col = nt * 8 + 2 * tq;
        u32 h01, l01, h23, l23;
        pack2(oacc[nt][0] * inv0, oacc[nt][1] * inv0, h01, l01);
        pack2(oacc[nt][2] * inv1, oacc[nt][3] * inv1, h23, l23);
        *(u32*)(Oh + a0 + col) = h01;
        *(u32*)(Ol + a0 + col) = l01;
        *(u32*)(Oh + a8 + col) = h23;
        *(u32*)(Ol + a8 + col) = l23;
    }
}

// ---------------- fused residual add + LayerNorm (+ optional hi/lo split out) ----------------
__global__ void __launch_bounds__(256) add_ln_kernel(
    const float* __restrict__ x, const float* __restrict__ res,
    const float* __restrict__ gamma, const float* __restrict__ beta,
    float* __restrict__ out, __half* __restrict__ oh, __half* __restrict__ ol,
    int split)
{
    __shared__ float row[D_];
    __shared__ float red[256];
    int r = blockIdx.x, t = threadIdx.x;
    const float* xr = x   + (size_t)r * D_;
    const float* rr = res + (size_t)r * D_;

    float s = 0.f;
    for (int i = t; i < D_; i += 256) {
        float v = xr[i] + rr[i];
        row[i] = v;
        s += v;
    }
    red[t] = s;
    __syncthreads();
    for (int o = 128; o > 0; o >>= 1) {
        if (t < o) red[t] += red[t + o];
        __syncthreads();
    }
    float mean = red[0] * (1.f / D_);
    __syncthreads();

    float vs = 0.f;
    for (int i = t; i < D_; i += 256) {
        float d = row[i] - mean;
        vs += d * d;
    }
    red[t] = vs;
    __syncthreads();
    for (int o = 128; o > 0; o >>= 1) {
        if (t < o) red[t] += red[t + o];
        __syncthreads();
    }
    float inv = rsqrtf(red[0] * (1.f / (D_ - 1)) + 1e-12f);

    for (int i = t; i < D_; i += 256) {
        float v = gamma[i] * (row[i] - mean) * inv + beta[i];
        out[(size_t)r * D_ + i] = v;
        if (split) {
            __half hh = __float2half_rn(v);
            oh[(size_t)r * D_ + i] = hh;
            ol[(size_t)r * D_ + i] = __float2half_rn(v - __half2float(hh));
        }
    }
}

// ---------------- host orchestration ----------------
static void run_gemmh(const __half* ah, const __half* al,
                      const __half* wh, const __half* wl,
                      const float* bias, float* C, __half* Ch, __half* Cl,
                      int N, int K, int relu, int mode)
{
    dim3 grid(N / 256, M_ / 128);
    gemmh_kernel<<<grid, 256, GSMEM>>>(ah, al, wh, wl, bias, C, Ch, Cl, N, K, relu, mode);
}

extern "C" void kernel_launch(void* const* d_in, const int* in_sizes, int n_in,
                              void* d_out, int out_size)
{
    const float* dec   = (const float*)d_in[0];
    const float* enc   = (const float*)d_in[1];
    // d_in[2] = mask (deterministic causal tril) — applied analytically
    const float* sa_wq = (const float*)d_in[3];
    const float* sa_wk = (const float*)d_in[4];
    const float* sa_wv = (const float*)d_in[5];
    const float* sa_bq = (const float*)d_in[6];
    const float* sa_bk = (const float*)d_in[7];
    const float* sa_bv = (const float*)d_in[8];
    const float* sa_wo = (const float*)d_in[9];
    const float* sa_bo = (const float*)d_in[10];
    const float* ca_wq = (const float*)d_in[11];
    const float* ca_wk = (const float*)d_in[12];
    const float* ca_wv = (const float*)d_in[13];
    const float* ca_bq = (const float*)d_in[14];
    const float* ca_bk = (const float*)d_in[15];
    const float* ca_bv = (const float*)d_in[16];
    const float* ca_wo = (const float*)d_in[17];
    const float* ca_bo = (const float*)d_in[18];
    const float* ff_w1 = (const float*)d_in[19];
    const float* ff_b1 = (const float*)d_in[20];
    const float* ff_w2 = (const float*)d_in[21];
    const float* ff_b2 = (const float*)d_in[22];
    const float* ln1g  = (const float*)d_in[23];
    const float* ln1b  = (const float*)d_in[24];
    const float* ln2g  = (const float*)d_in[25];
    const float* ln2b  = (const float*)d_in[26];
    const float* ln3g  = (const float*)d_in[27];
    const float* ln3b  = (const float*)d_in[28];
    float* out = (float*)d_out;

    float *tmp, *o1, *o2;
    __half *ah, *al, *wh, *wl, *qh, *ql, *kh, *kl, *vh, *vl, *fh, *fl;
    cudaGetSymbolAddress((void**)&tmp, g_tmp);
    cudaGetSymbolAddress((void**)&o1,  g_o1);
    cudaGetSymbolAddress((void**)&o2,  g_o2);
    cudaGetSymbolAddress((void**)&ah,  g_ah);
    cudaGetSymbolAddress((void**)&al,  g_al);
    cudaGetSymbolAddress((void**)&wh,  g_wh);
    cudaGetSymbolAddress((void**)&wl,  g_wl);
    cudaGetSymbolAddress((void**)&qh,  g_qh);
    cudaGetSymbolAddress((void**)&ql,  g_ql);
    cudaGetSymbolAddress((void**)&kh,  g_kh);
    cudaGetSymbolAddress((void**)&kl,  g_kl);
    cudaGetSymbolAddress((void**)&vh,  g_vh);
    cudaGetSymbolAddress((void**)&vl,  g_vl);
    cudaGetSymbolAddress((void**)&fh,  g_fh);
    cudaGetSymbolAddress((void**)&fl,  g_fl);

    cudaFuncSetAttribute(gemmh_kernel, cudaFuncAttributeMaxDynamicSharedMemorySize, GSMEM);
    cudaFuncSetAttribute(attn_tc_kernel, cudaFuncAttributeMaxDynamicSharedMemorySize, ASMEM);

    dim3 tb(32, 32);
    dim3 tqkvGrid(D_ / 32, DH_ / 32, H_);
    dim3 attnGrid(S_ / 128, H_, B_);
    const int rs4M = (M_ * D_) / 1024;

    // ===== self-attention =====
    round_split_h<<<rs4M, 256>>>(dec, ah, al);
    tqkv_split_h<<<tqkvGrid, tb>>>(sa_wq, wh, wl);
    run_gemmh(ah, al, wh, wl, sa_bq, 0, qh, ql, D_, D_, 0, 1);
    tqkv_split_h<<<tqkvGrid, tb>>>(sa_wk, wh, wl);
    run_gemmh(ah, al, wh, wl, sa_bk, 0, kh, kl, D_, D_, 0, 1);
    tqkv_split_h<<<tqkvGrid, tb>>>(sa_wv, wh, wl);
    run_gemmh(ah, al, wh, wl, sa_bv, 0, vh, vl, D_, D_, 0, 1);
    attn_tc_kernel<<<attnGrid, 256, ASMEM>>>(qh, ql, kh, kl, vh, vl, ah, al, 1);
    trans_split_h<<<dim3(D_ / 32, D_ / 32), tb>>>(sa_wo, wh, wl, D_, D_);
    run_gemmh(ah, al, wh, wl, sa_bo, tmp, 0, 0, D_, D_, 0, 0);
    add_ln_kernel<<<M_, 256>>>(tmp, dec, ln1g, ln1b, o1, ah, al, 1);

    // ===== cross-attention =====
    tqkv_split_h<<<tqkvGrid, tb>>>(ca_wq, wh, wl);
    run_gemmh(ah, al, wh, wl, ca_bq, 0, qh, ql, D_, D_, 0, 1);
    round_split_h<<<rs4M, 256>>>(enc, ah, al);
    tqkv_split_h<<<tqkvGrid, tb>>>(ca_wk, wh, wl);
    run_gemmh(ah, al, wh, wl, ca_bk, 0, kh, kl, D_, D_, 0, 1);
    tqkv_split_h<<<tqkvGrid, tb>>>(ca_wv, wh, wl);
    run_gemmh(ah, al, wh, wl, ca_bv, 0, vh, vl, D_, D_, 0, 1);
    attn_tc_kernel<<<attnGrid, 256, ASMEM>>>(qh, ql, kh, kl, vh, vl, ah, al, 0);
    trans_split_h<<<dim3(D_ / 32, D_ / 32), tb>>>(ca_wo, wh, wl, D_, D_);
    run_gemmh(ah, al, wh, wl, ca_bo, tmp, 0, 0, D_, D_, 0, 0);
    add_ln_kernel<<<M_, 256>>>(tmp, o1, ln2g, ln2b, o2, ah, al, 1);

    // ===== feed-forward =====
    trans_split_h<<<dim3(F_ / 32, D_ / 32), tb>>>(ff_w1, wh, wl, D_, F_);
    run_gemmh(ah, al, wh, wl, ff_b1, 0, fh, fl, F_, D_, 1, 1);   // + ReLU, hi/lo out
    trans_split_h<<<dim3(D_ / 32, F_ / 32), tb>>>(ff_w2, wh, wl, F_, D_);
    run_gemmh(fh, fl, wh, wl, ff_b2, tmp, 0, 0, D_, F_, 0, 0);
    add_ln_kernel<<<M_, 256>>>(tmp, o2, ln3g, ln3b, out, 0, 0, 0);
}